// round 1
// baseline (speedup 1.0000x reference)
#include <cuda_runtime.h>
#include <math.h>
#include <stdint.h>

#define SEQ 2048
#define HID 2048
#define NH 16
#define NKV 4
#define HD 128
#define QD (NH*HD)    /* 2048 */
#define KVD (NKV*HD)  /* 512  */

// Scratch (device globals: no allocations allowed)
__device__ float g_q[SEQ*QD];
__device__ float g_k[SEQ*KVD];
__device__ float g_v[SEQ*KVD];
__device__ float g_o[SEQ*QD];

// ---------------------------------------------------------------------------
// GEMM: C[M,N] = A[M,K] @ B[N,K]^T  (+ A2[M,K] @ B2[N,K]^T when HAS_MU)
// 128x128 tiles, BK=8, 256 threads, 8x8 register micro-tiles (split-64 cols)
// ---------------------------------------------------------------------------
template<bool HAS_MU>
__global__ __launch_bounds__(256) void gemm_tn(
    const float* __restrict__ A, const float* __restrict__ A2,
    const float* __restrict__ B, const float* __restrict__ B2,
    float* __restrict__ C, int M, int N, int K)
{
    __shared__ float As[8][128];
    __shared__ float Bs[8][128];

    const int tid = threadIdx.x;
    const int tx = tid & 15;        // 0..15 -> column group
    const int ty = tid >> 4;        // 0..15 -> row group
    const int row0 = blockIdx.y * 128;
    const int col0 = blockIdx.x * 128;

    const int lr = tid >> 1;          // 0..127: tile row loaded by this thread
    const int lk = (tid & 1) << 2;    // 0 or 4: k offset within BK=8

    float acc[8][8];
#pragma unroll
    for (int i = 0; i < 8; ++i)
#pragma unroll
        for (int j = 0; j < 8; ++j) acc[i][j] = 0.0f;

    const int ntiles = (HAS_MU ? (2 * K) : K) >> 3;

    // prefetch tile 0 (kpos = 0 always in first operand set)
    float4 areg = *(const float4*)(A + (size_t)(row0 + lr) * K + lk);
    float4 breg = *(const float4*)(B + (size_t)(col0 + lr) * K + lk);

    for (int t = 0; t < ntiles; ++t) {
        As[lk + 0][lr] = areg.x; As[lk + 1][lr] = areg.y;
        As[lk + 2][lr] = areg.z; As[lk + 3][lr] = areg.w;
        Bs[lk + 0][lr] = breg.x; Bs[lk + 1][lr] = breg.y;
        Bs[lk + 2][lr] = breg.z; Bs[lk + 3][lr] = breg.w;
        __syncthreads();

        if (t + 1 < ntiles) {
            int kpos = (t + 1) << 3;
            const float* Ab = A; const float* Bb = B;
            if (HAS_MU && kpos >= K) { Ab = A2; Bb = B2; kpos -= K; }
            areg = *(const float4*)(Ab + (size_t)(row0 + lr) * K + kpos + lk);
            breg = *(const float4*)(Bb + (size_t)(col0 + lr) * K + kpos + lk);
        }

#pragma unroll
        for (int kk = 0; kk < 8; ++kk) {
            float a[8], b[8];
            *(float4*)&a[0] = *(const float4*)&As[kk][ty * 4];
            *(float4*)&a[4] = *(const float4*)&As[kk][64 + ty * 4];
            *(float4*)&b[0] = *(const float4*)&Bs[kk][tx * 4];
            *(float4*)&b[4] = *(const float4*)&Bs[kk][64 + tx * 4];
#pragma unroll
            for (int i = 0; i < 8; ++i)
#pragma unroll
                for (int j = 0; j < 8; ++j)
                    acc[i][j] = fmaf(a[i], b[j], acc[i][j]);
        }
        __syncthreads();
    }

#pragma unroll
    for (int i = 0; i < 8; ++i) {
        int r = row0 + ((i < 4) ? (ty * 4 + i) : (64 + ty * 4 + (i - 4)));
        float4 v0 = make_float4(acc[i][0], acc[i][1], acc[i][2], acc[i][3]);
        float4 v1 = make_float4(acc[i][4], acc[i][5], acc[i][6], acc[i][7]);
        *(float4*)(C + (size_t)r * N + col0 + tx * 4)      = v0;
        *(float4*)(C + (size_t)r * N + col0 + 64 + tx * 4) = v1;
    }
}

// ---------------------------------------------------------------------------
// Per-head RMSNorm + RoPE (in place on g_q / g_k). grid=(SEQ, NH+NKV), 128 thr
// ---------------------------------------------------------------------------
__global__ __launch_bounds__(128) void normrope_kernel(
    float* __restrict__ qb, float* __restrict__ kb,
    const float* __restrict__ qw, const float* __restrict__ kw)
{
    const int pos = blockIdx.x;
    const int hh = blockIdx.y;
    const int d = threadIdx.x;

    float* buf; int stride, col0; const float* w;
    if (hh < NH) { buf = qb; stride = QD;  col0 = hh * HD;        w = qw; }
    else         { buf = kb; stride = KVD; col0 = (hh - NH) * HD; w = kw; }

    const size_t idx = (size_t)pos * stride + col0 + d;
    float x = buf[idx];

    float ss = x * x;
#pragma unroll
    for (int off = 16; off; off >>= 1) ss += __shfl_xor_sync(0xffffffffu, ss, off);

    __shared__ float red[4];
    __shared__ float xs[128];
    if ((d & 31) == 0) red[d >> 5] = ss;
    __syncthreads();
    ss = red[0] + red[1] + red[2] + red[3];

    float xn = x * rsqrtf(ss * (1.0f / 128.0f) + 1e-6f) * w[d];
    xs[d] = xn;
    __syncthreads();
    float rot = (d < 64) ? -xs[d + 64] : xs[d - 64];

    float fi = (float)(d & 63);
    float ang = (float)pos * powf(10000.0f, -fi * (1.0f / 64.0f));
    float sn, cs;
    sincosf(ang, &sn, &cs);
    buf[idx] = xn * cs + rot * sn;
}

// ---------------------------------------------------------------------------
// Causal flash attention, fp32. 64 queries x 64 keys per tile, D=128.
// grid = (SEQ/64, NH), 256 threads. Dynamic smem.
// ---------------------------------------------------------------------------
__global__ __launch_bounds__(256) void attn_kernel(
    const float* __restrict__ q, const float* __restrict__ k,
    const float* __restrict__ v, float* __restrict__ o)
{
    extern __shared__ float sm[];
    float (*Qs)[129] = (float(*)[129])(sm);                         // 64 x 129
    float (*Ks)[129] = (float(*)[129])(sm + 64 * 129);              // 64 x 129
    float (*Vs)[128] = (float(*)[128])(sm + 2 * 64 * 129);          // 64 x 128
    float (*Ps)[65]  = (float(*)[65]) (sm + 2 * 64 * 129 + 64 * 128); // 64 x 65 [col][row]

    const int qt = blockIdx.x;
    const int h = blockIdx.y;
    const int kvh = h >> 2;
    const int row0 = qt * 64;
    const int tid = threadIdx.x;
    const int tx = tid & 15, ty = tid >> 4;

    // Load Q tile (rows row0..row0+63, this head's 128 dims)
    for (int i = tid; i < 64 * 32; i += 256) {
        int r = i >> 5, c = (i & 31) << 2;
        float4 val = *(const float4*)(q + (size_t)(row0 + r) * QD + h * HD + c);
        Qs[r][c] = val.x; Qs[r][c + 1] = val.y; Qs[r][c + 2] = val.z; Qs[r][c + 3] = val.w;
    }

    float m[4], l[4], acc[4][8];
#pragma unroll
    for (int i = 0; i < 4; ++i) {
        m[i] = -1e30f; l[i] = 0.0f;
#pragma unroll
        for (int j = 0; j < 8; ++j) acc[i][j] = 0.0f;
    }
    const float scale = 0.08838834764831845f;  // 1/sqrt(128)

    for (int jt = 0; jt <= qt; ++jt) {
        __syncthreads();  // protect Ks/Vs/Ps from previous iteration reads
        for (int i = tid; i < 64 * 32; i += 256) {
            int r = i >> 5, c = (i & 31) << 2;
            size_t base = (size_t)(jt * 64 + r) * KVD + kvh * HD + c;
            float4 kv = *(const float4*)(k + base);
            Ks[r][c] = kv.x; Ks[r][c + 1] = kv.y; Ks[r][c + 2] = kv.z; Ks[r][c + 3] = kv.w;
            *(float4*)&Vs[r][c] = *(const float4*)(v + base);
        }
        __syncthreads();

        // S = Q @ K^T  (4x4 per thread)
        float s[4][4];
#pragma unroll
        for (int i = 0; i < 4; ++i)
#pragma unroll
            for (int j = 0; j < 4; ++j) s[i][j] = 0.0f;

#pragma unroll 8
        for (int kk = 0; kk < 128; ++kk) {
            float a0 = Qs[ty * 4 + 0][kk], a1 = Qs[ty * 4 + 1][kk];
            float a2 = Qs[ty * 4 + 2][kk], a3 = Qs[ty * 4 + 3][kk];
            float b0 = Ks[tx * 4 + 0][kk], b1 = Ks[tx * 4 + 1][kk];
            float b2 = Ks[tx * 4 + 2][kk], b3 = Ks[tx * 4 + 3][kk];
            s[0][0] = fmaf(a0, b0, s[0][0]); s[0][1] = fmaf(a0, b1, s[0][1]);
            s[0][2] = fmaf(a0, b2, s[0][2]); s[0][3] = fmaf(a0, b3, s[0][3]);
            s[1][0] = fmaf(a1, b0, s[1][0]); s[1][1] = fmaf(a1, b1, s[1][1]);
            s[1][2] = fmaf(a1, b2, s[1][2]); s[1][3] = fmaf(a1, b3, s[1][3]);
            s[2][0] = fmaf(a2, b0, s[2][0]); s[2][1] = fmaf(a2, b1, s[2][1]);
            s[2][2] = fmaf(a2, b2, s[2][2]); s[2][3] = fmaf(a2, b3, s[2][3]);
            s[3][0] = fmaf(a3, b0, s[3][0]); s[3][1] = fmaf(a3, b1, s[3][1]);
            s[3][2] = fmaf(a3, b2, s[3][2]); s[3][3] = fmaf(a3, b3, s[3][3]);
        }

        // scale + causal mask (only diagonal tile is partial)
#pragma unroll
        for (int ii = 0; ii < 4; ++ii)
#pragma unroll
            for (int jj = 0; jj < 4; ++jj) {
                float sv = s[ii][jj] * scale;
                if (jt == qt) {
                    int cg = jt * 64 + tx * 4 + jj;
                    int rg = row0 + ty * 4 + ii;
                    if (cg > rg) sv = -1e30f;
                }
                s[ii][jj] = sv;
            }

        // online softmax update (row stats across 16-lane tx groups via shfl)
#pragma unroll
        for (int ii = 0; ii < 4; ++ii) {
            float mx = fmaxf(fmaxf(s[ii][0], s[ii][1]), fmaxf(s[ii][2], s[ii][3]));
#pragma unroll
            for (int off = 8; off; off >>= 1) mx = fmaxf(mx, __shfl_xor_sync(0xffffffffu, mx, off));
            float mnew = fmaxf(m[ii], mx);
            float alpha = __expf(m[ii] - mnew);
            float ls = 0.0f;
#pragma unroll
            for (int jj = 0; jj < 4; ++jj) {
                float p = __expf(s[ii][jj] - mnew);
                Ps[tx * 4 + jj][ty * 4 + ii] = p;
                ls += p;
            }
#pragma unroll
            for (int off = 8; off; off >>= 1) ls += __shfl_xor_sync(0xffffffffu, ls, off);
            l[ii] = l[ii] * alpha + ls;
            m[ii] = mnew;
#pragma unroll
            for (int c = 0; c < 8; ++c) acc[ii][c] *= alpha;
        }
        __syncthreads();

        // O += P @ V   (cols {4tx..4tx+3, 64+4tx..64+4tx+3})
#pragma unroll 4
        for (int j = 0; j < 64; ++j) {
            float4 va = *(const float4*)&Vs[j][tx * 4];
            float4 vb = *(const float4*)&Vs[j][64 + tx * 4];
#pragma unroll
            for (int ii = 0; ii < 4; ++ii) {
                float p = Ps[j][ty * 4 + ii];
                acc[ii][0] = fmaf(p, va.x, acc[ii][0]);
                acc[ii][1] = fmaf(p, va.y, acc[ii][1]);
                acc[ii][2] = fmaf(p, va.z, acc[ii][2]);
                acc[ii][3] = fmaf(p, va.w, acc[ii][3]);
                acc[ii][4] = fmaf(p, vb.x, acc[ii][4]);
                acc[ii][5] = fmaf(p, vb.y, acc[ii][5]);
                acc[ii][6] = fmaf(p, vb.z, acc[ii][6]);
                acc[ii][7] = fmaf(p, vb.w, acc[ii][7]);
            }
        }
    }

    // normalize + write to g_o in [s, h*128+d] layout
#pragma unroll
    for (int ii = 0; ii < 4; ++ii) {
        float inv = 1.0f / l[ii];
        size_t r = (size_t)(row0 + ty * 4 + ii);
        float4 v0 = make_float4(acc[ii][0] * inv, acc[ii][1] * inv, acc[ii][2] * inv, acc[ii][3] * inv);
        float4 v1 = make_float4(acc[ii][4] * inv, acc[ii][5] * inv, acc[ii][6] * inv, acc[ii][7] * inv);
        *(float4*)(o + r * QD + h * HD + tx * 4)      = v0;
        *(float4*)(o + r * QD + h * HD + 64 + tx * 4) = v1;
    }
}

// ---------------------------------------------------------------------------
extern "C" void kernel_launch(void* const* d_in, const int* in_sizes, int n_in,
                              void* d_out, int out_size)
{
    (void)in_sizes; (void)n_in; (void)out_size;
    const float* x   = (const float*)d_in[0];
    const float* mu  = (const float*)d_in[1];
    const float* wq  = (const float*)d_in[2];
    const float* wk  = (const float*)d_in[3];
    const float* wv  = (const float*)d_in[4];
    const float* wo  = (const float*)d_in[5];
    const float* wmq = (const float*)d_in[6];
    const float* wmk = (const float*)d_in[7];
    const float* wmv = (const float*)d_in[8];
    const float* qw  = (const float*)d_in[9];
    const float* kw  = (const float*)d_in[10];
    float* out = (float*)d_out;

    float *pq, *pk, *pv, *po;
    cudaGetSymbolAddress((void**)&pq, g_q);
    cudaGetSymbolAddress((void**)&pk, g_k);
    cudaGetSymbolAddress((void**)&pv, g_v);
    cudaGetSymbolAddress((void**)&po, g_o);

    // QKV projections (with mu term folded as a second K-range)
    gemm_tn<true><<<dim3(QD / 128, SEQ / 128), 256>>>(x, mu, wq, wmq, pq, SEQ, QD, HID);
    gemm_tn<true><<<dim3(KVD / 128, SEQ / 128), 256>>>(x, mu, wk, wmk, pk, SEQ, KVD, HID);
    gemm_tn<true><<<dim3(KVD / 128, SEQ / 128), 256>>>(x, mu, wv, wmv, pv, SEQ, KVD, HID);

    // per-head RMSNorm + RoPE on q and k
    normrope_kernel<<<dim3(SEQ, NH + NKV), 128>>>(pq, pk, qw, kw);

    // causal GQA attention
    const size_t smem = (size_t)(2 * 64 * 129 + 64 * 128 + 64 * 65) * sizeof(float);
    cudaFuncSetAttribute(attn_kernel, cudaFuncAttributeMaxDynamicSharedMemorySize, (int)smem);
    attn_kernel<<<dim3(SEQ / 64, NH), 256, smem>>>(pq, pk, pv, po);

    // output projection
    gemm_tn<false><<<dim3(QD / 128, SEQ / 128), 256>>>(po, nullptr, wo, nullptr, out, SEQ, QD, HID);
}

// round 3
// speedup vs baseline: 2.4344x; 2.4344x over previous
#include <cuda_runtime.h>
#include <math.h>
#include <stdint.h>

#define SEQ 2048
#define HID 2048
#define NH 16
#define NKV 4
#define HD 128
#define QD (NH*HD)    /* 2048 */
#define KVD (NKV*HD)  /* 512  */

// Scratch (device globals: no allocations allowed)
__device__ float g_q[SEQ*QD];
__device__ float g_k[SEQ*KVD];
__device__ float g_v[SEQ*KVD];
__device__ float g_o[SEQ*QD];

// ---------------------------------------------------------------------------
// tf32 helpers (plain sm_80+ PTX — no sm_103a-gated instructions)
// ---------------------------------------------------------------------------
__device__ __forceinline__ uint32_t f2tf32(float x) {
    uint32_t r;
    asm("cvt.rna.tf32.f32 %0, %1;" : "=r"(r) : "f"(x));
    return r;
}

__device__ __forceinline__ void mma_tf32(float d[4], const uint32_t a[4], const uint32_t b[2]) {
    asm volatile(
        "mma.sync.aligned.m16n8k8.row.col.f32.tf32.tf32.f32 "
        "{%0,%1,%2,%3}, {%4,%5,%6,%7}, {%8,%9}, {%0,%1,%2,%3};"
        : "+f"(d[0]), "+f"(d[1]), "+f"(d[2]), "+f"(d[3])
        : "r"(a[0]), "r"(a[1]), "r"(a[2]), "r"(a[3]), "r"(b[0]), "r"(b[1]));
}

// ---------------------------------------------------------------------------
// Core tf32 MMA GEMM tile: C[128,128] = Ablk[128,K] @ Bblk[128,K]^T
// (+ A2blk @ B2blk^T when HAS_MU). 256 threads, BK=32, double-buffered SMEM.
// SMEM layout per buffer: A[128][36] words then B[128][36] words (tf32 bits).
// ---------------------------------------------------------------------------
#define BUF_WORDS (128 * 36)

template<bool HAS_MU>
__device__ __forceinline__ void gemm_core(
    const float* __restrict__ Ablk, const float* __restrict__ A2blk,
    const float* __restrict__ Bblk, const float* __restrict__ B2blk,
    float* __restrict__ Cblk, int ldc, int K, char* smem)
{
    uint32_t* s = (uint32_t*)smem;

    const int tid = threadIdx.x;
    const int wid = tid >> 5, lane = tid & 31;
    const int g = lane >> 2, t = lane & 3;
    const int m0 = (wid >> 2) * 64;   // warp row base (2 warps along M)
    const int n0 = (wid & 3) * 32;    // warp col base (4 warps along N)

    const int r  = tid >> 1;          // unused placeholder removed below
    (void)r;

    float acc[4][4][4];
#pragma unroll
    for (int i = 0; i < 4; ++i)
#pragma unroll
        for (int j = 0; j < 4; ++j)
#pragma unroll
            for (int q = 0; q < 4; ++q) acc[i][j][q] = 0.0f;

    const int nch = (HAS_MU ? 2 * K : K) >> 5;

    // prefetch chunk 0
    float4 pa[4], pb[4];
#pragma unroll
    for (int i = 0; i < 4; ++i) {
        int idx = tid + i * 256;
        int rr = idx >> 3, c4 = idx & 7;
        pa[i] = *(const float4*)(Ablk + (size_t)rr * K + c4 * 4);
        pb[i] = *(const float4*)(Bblk + (size_t)rr * K + c4 * 4);
    }

    for (int c = 0; c < nch; ++c) {
        const int buf = c & 1;
        uint32_t* sA = s + buf * (2 * BUF_WORDS);
        uint32_t* sB = sA + BUF_WORDS;

        // store prefetched chunk (converted to tf32 bits)
#pragma unroll
        for (int i = 0; i < 4; ++i) {
            int idx = tid + i * 256;
            int rr = idx >> 3, c4 = idx & 7;
            uint4 ua = make_uint4(f2tf32(pa[i].x), f2tf32(pa[i].y), f2tf32(pa[i].z), f2tf32(pa[i].w));
            uint4 ub = make_uint4(f2tf32(pb[i].x), f2tf32(pb[i].y), f2tf32(pb[i].z), f2tf32(pb[i].w));
            *(uint4*)(sA + rr * 36 + c4 * 4) = ua;
            *(uint4*)(sB + rr * 36 + c4 * 4) = ub;
        }
        __syncthreads();

        // prefetch next chunk
        if (c + 1 < nch) {
            int kk = (c + 1) << 5;
            const float* Ap = Ablk; const float* Bp = Bblk;
            if (HAS_MU && kk >= K) { Ap = A2blk; Bp = B2blk; kk -= K; }
#pragma unroll
            for (int i = 0; i < 4; ++i) {
                int idx = tid + i * 256;
                int rr = idx >> 3, c4 = idx & 7;
                pa[i] = *(const float4*)(Ap + (size_t)rr * K + kk + c4 * 4);
                pb[i] = *(const float4*)(Bp + (size_t)rr * K + kk + c4 * 4);
            }
        }

        // 4 k-steps of m16n8k8
#pragma unroll
        for (int ks = 0; ks < 4; ++ks) {
            uint32_t af[4][4], bf[4][2];
#pragma unroll
            for (int mt = 0; mt < 4; ++mt) {
                int mr = m0 + mt * 16 + g;
                af[mt][0] = sA[mr * 36 + ks * 8 + t];
                af[mt][1] = sA[(mr + 8) * 36 + ks * 8 + t];
                af[mt][2] = sA[mr * 36 + ks * 8 + t + 4];
                af[mt][3] = sA[(mr + 8) * 36 + ks * 8 + t + 4];
            }
#pragma unroll
            for (int nt = 0; nt < 4; ++nt) {
                int nr = n0 + nt * 8 + g;
                bf[nt][0] = sB[nr * 36 + ks * 8 + t];
                bf[nt][1] = sB[nr * 36 + ks * 8 + t + 4];
            }
#pragma unroll
            for (int mt = 0; mt < 4; ++mt)
#pragma unroll
                for (int nt = 0; nt < 4; ++nt)
                    mma_tf32(acc[mt][nt], af[mt], bf[nt]);
        }
        __syncthreads();
    }

    // epilogue: fragment rows g / g+8, cols 2t / 2t+1
#pragma unroll
    for (int mt = 0; mt < 4; ++mt) {
        int r0 = m0 + mt * 16 + g;
#pragma unroll
        for (int nt = 0; nt < 4; ++nt) {
            int cc = n0 + nt * 8 + 2 * t;
            *(float2*)(Cblk + (size_t)r0 * ldc + cc)       = make_float2(acc[mt][nt][0], acc[mt][nt][1]);
            *(float2*)(Cblk + (size_t)(r0 + 8) * ldc + cc) = make_float2(acc[mt][nt][2], acc[mt][nt][3]);
        }
    }
}

// Fused QKV projection: grid = (24, 16). Col blocks 0..15 -> Q, 16..19 -> K, 20..23 -> V.
__global__ __launch_bounds__(256) void qkv_mma(
    const float* __restrict__ x, const float* __restrict__ mu,
    const float* __restrict__ wq, const float* __restrict__ wmq,
    const float* __restrict__ wk, const float* __restrict__ wmk,
    const float* __restrict__ wv, const float* __restrict__ wmv,
    float* __restrict__ pq, float* __restrict__ pk, float* __restrict__ pv)
{
    extern __shared__ char smem[];
    const int cb = blockIdx.x;
    const int row0 = blockIdx.y * 128;

    const float *B, *B2; float* C; int ldc, ccol;
    if (cb < 16)      { B = wq; B2 = wmq; C = pq; ldc = QD;  ccol = cb * 128; }
    else if (cb < 20) { B = wk; B2 = wmk; C = pk; ldc = KVD; ccol = (cb - 16) * 128; }
    else              { B = wv; B2 = wmv; C = pv; ldc = KVD; ccol = (cb - 20) * 128; }

    gemm_core<true>(x + (size_t)row0 * HID, mu + (size_t)row0 * HID,
                    B + (size_t)ccol * HID, B2 + (size_t)ccol * HID,
                    C + (size_t)row0 * ldc + ccol, ldc, HID, smem);
}

// Output projection: grid = (16, 16)
__global__ __launch_bounds__(256) void oproj_mma(
    const float* __restrict__ A, const float* __restrict__ B, float* __restrict__ C)
{
    extern __shared__ char smem[];
    const int row0 = blockIdx.y * 128;
    const int ccol = blockIdx.x * 128;
    gemm_core<false>(A + (size_t)row0 * QD, nullptr,
                     B + (size_t)ccol * QD, nullptr,
                     C + (size_t)row0 * QD + ccol, QD, QD, smem);
}

// ---------------------------------------------------------------------------
// Per-head RMSNorm + RoPE (in place on g_q / g_k). grid=(SEQ, NH+NKV), 128 thr
// ---------------------------------------------------------------------------
__global__ __launch_bounds__(128) void normrope_kernel(
    float* __restrict__ qb, float* __restrict__ kb,
    const float* __restrict__ qw, const float* __restrict__ kw)
{
    const int pos = blockIdx.x;
    const int hh = blockIdx.y;
    const int d = threadIdx.x;

    float* buf; int stride, col0; const float* w;
    if (hh < NH) { buf = qb; stride = QD;  col0 = hh * HD;        w = qw; }
    else         { buf = kb; stride = KVD; col0 = (hh - NH) * HD; w = kw; }

    const size_t idx = (size_t)pos * stride + col0 + d;
    float x = buf[idx];

    float ss = x * x;
#pragma unroll
    for (int off = 16; off; off >>= 1) ss += __shfl_xor_sync(0xffffffffu, ss, off);

    __shared__ float red[4];
    __shared__ float xs[128];
    if ((d & 31) == 0) red[d >> 5] = ss;
    __syncthreads();
    ss = red[0] + red[1] + red[2] + red[3];

    float xn = x * rsqrtf(ss * (1.0f / 128.0f) + 1e-6f) * w[d];
    xs[d] = xn;
    __syncthreads();
    float rot = (d < 64) ? -xs[d + 64] : xs[d - 64];

    float fi = (float)(d & 63);
    float ang = (float)pos * powf(10000.0f, -fi * (1.0f / 64.0f));
    float sn, cs;
    sincosf(ang, &sn, &cs);
    buf[idx] = xn * cs + rot * sn;
}

// ---------------------------------------------------------------------------
// Causal flash attention, fp32. 64 queries x 64 keys per tile, D=128.
// grid = (SEQ/64, NH), 256 threads. Dynamic smem.
// ---------------------------------------------------------------------------
__global__ __launch_bounds__(256) void attn_kernel(
    const float* __restrict__ q, const float* __restrict__ k,
    const float* __restrict__ v, float* __restrict__ o)
{
    extern __shared__ float sm[];
    float (*Qs)[129] = (float(*)[129])(sm);                         // 64 x 129
    float (*Ks)[129] = (float(*)[129])(sm + 64 * 129);              // 64 x 129
    float (*Vs)[128] = (float(*)[128])(sm + 2 * 64 * 129);          // 64 x 128
    float (*Ps)[65]  = (float(*)[65]) (sm + 2 * 64 * 129 + 64 * 128); // 64 x 65 [col][row]

    const int qt = blockIdx.x;
    const int h = blockIdx.y;
    const int kvh = h >> 2;
    const int row0 = qt * 64;
    const int tid = threadIdx.x;
    const int tx = tid & 15, ty = tid >> 4;

    for (int i = tid; i < 64 * 32; i += 256) {
        int r = i >> 5, c = (i & 31) << 2;
        float4 val = *(const float4*)(q + (size_t)(row0 + r) * QD + h * HD + c);
        Qs[r][c] = val.x; Qs[r][c + 1] = val.y; Qs[r][c + 2] = val.z; Qs[r][c + 3] = val.w;
    }

    float m[4], l[4], acc[4][8];
#pragma unroll
    for (int i = 0; i < 4; ++i) {
        m[i] = -1e30f; l[i] = 0.0f;
#pragma unroll
        for (int j = 0; j < 8; ++j) acc[i][j] = 0.0f;
    }
    const float scale = 0.08838834764831845f;  // 1/sqrt(128)

    for (int jt = 0; jt <= qt; ++jt) {
        __syncthreads();
        for (int i = tid; i < 64 * 32; i += 256) {
            int r = i >> 5, c = (i & 31) << 2;
            size_t base = (size_t)(jt * 64 + r) * KVD + kvh * HD + c;
            float4 kv = *(const float4*)(k + base);
            Ks[r][c] = kv.x; Ks[r][c + 1] = kv.y; Ks[r][c + 2] = kv.z; Ks[r][c + 3] = kv.w;
            *(float4*)&Vs[r][c] = *(const float4*)(v + base);
        }
        __syncthreads();

        float s[4][4];
#pragma unroll
        for (int i = 0; i < 4; ++i)
#pragma unroll
            for (int j = 0; j < 4; ++j) s[i][j] = 0.0f;

#pragma unroll 8
        for (int kk = 0; kk < 128; ++kk) {
            float a0 = Qs[ty * 4 + 0][kk], a1 = Qs[ty * 4 + 1][kk];
            float a2 = Qs[ty * 4 + 2][kk], a3 = Qs[ty * 4 + 3][kk];
            float b0 = Ks[tx * 4 + 0][kk], b1 = Ks[tx * 4 + 1][kk];
            float b2 = Ks[tx * 4 + 2][kk], b3 = Ks[tx * 4 + 3][kk];
            s[0][0] = fmaf(a0, b0, s[0][0]); s[0][1] = fmaf(a0, b1, s[0][1]);
            s[0][2] = fmaf(a0, b2, s[0][2]); s[0][3] = fmaf(a0, b3, s[0][3]);
            s[1][0] = fmaf(a1, b0, s[1][0]); s[1][1] = fmaf(a1, b1, s[1][1]);
            s[1][2] = fmaf(a1, b2, s[1][2]); s[1][3] = fmaf(a1, b3, s[1][3]);
            s[2][0] = fmaf(a2, b0, s[2][0]); s[2][1] = fmaf(a2, b1, s[2][1]);
            s[2][2] = fmaf(a2, b2, s[2][2]); s[2][3] = fmaf(a2, b3, s[2][3]);
            s[3][0] = fmaf(a3, b0, s[3][0]); s[3][1] = fmaf(a3, b1, s[3][1]);
            s[3][2] = fmaf(a3, b2, s[3][2]); s[3][3] = fmaf(a3, b3, s[3][3]);
        }

#pragma unroll
        for (int ii = 0; ii < 4; ++ii)
#pragma unroll
            for (int jj = 0; jj < 4; ++jj) {
                float sv = s[ii][jj] * scale;
                if (jt == qt) {
                    int cg = jt * 64 + tx * 4 + jj;
                    int rg = row0 + ty * 4 + ii;
                    if (cg > rg) sv = -1e30f;
                }
                s[ii][jj] = sv;
            }

#pragma unroll
        for (int ii = 0; ii < 4; ++ii) {
            float mx = fmaxf(fmaxf(s[ii][0], s[ii][1]), fmaxf(s[ii][2], s[ii][3]));
#pragma unroll
            for (int off = 8; off; off >>= 1) mx = fmaxf(mx, __shfl_xor_sync(0xffffffffu, mx, off));
            float mnew = fmaxf(m[ii], mx);
            float alpha = __expf(m[ii] - mnew);
            float ls = 0.0f;
#pragma unroll
            for (int jj = 0; jj < 4; ++jj) {
                float p = __expf(s[ii][jj] - mnew);
                Ps[tx * 4 + jj][ty * 4 + ii] = p;
                ls += p;
            }
#pragma unroll
            for (int off = 8; off; off >>= 1) ls += __shfl_xor_sync(0xffffffffu, ls, off);
            l[ii] = l[ii] * alpha + ls;
            m[ii] = mnew;
#pragma unroll
            for (int c = 0; c < 8; ++c) acc[ii][c] *= alpha;
        }
        __syncthreads();

#pragma unroll 4
        for (int j = 0; j < 64; ++j) {
            float4 va = *(const float4*)&Vs[j][tx * 4];
            float4 vb = *(const float4*)&Vs[j][64 + tx * 4];
#pragma unroll
            for (int ii = 0; ii < 4; ++ii) {
                float p = Ps[j][ty * 4 + ii];
                acc[ii][0] = fmaf(p, va.x, acc[ii][0]);
                acc[ii][1] = fmaf(p, va.y, acc[ii][1]);
                acc[ii][2] = fmaf(p, va.z, acc[ii][2]);
                acc[ii][3] = fmaf(p, va.w, acc[ii][3]);
                acc[ii][4] = fmaf(p, vb.x, acc[ii][4]);
                acc[ii][5] = fmaf(p, vb.y, acc[ii][5]);
                acc[ii][6] = fmaf(p, vb.z, acc[ii][6]);
                acc[ii][7] = fmaf(p, vb.w, acc[ii][7]);
            }
        }
    }

#pragma unroll
    for (int ii = 0; ii < 4; ++ii) {
        float inv = 1.0f / l[ii];
        size_t r = (size_t)(row0 + ty * 4 + ii);
        float4 v0 = make_float4(acc[ii][0] * inv, acc[ii][1] * inv, acc[ii][2] * inv, acc[ii][3] * inv);
        float4 v1 = make_float4(acc[ii][4] * inv, acc[ii][5] * inv, acc[ii][6] * inv, acc[ii][7] * inv);
        *(float4*)(o + r * QD + h * HD + tx * 4)      = v0;
        *(float4*)(o + r * QD + h * HD + 64 + tx * 4) = v1;
    }
}

// ---------------------------------------------------------------------------
extern "C" void kernel_launch(void* const* d_in, const int* in_sizes, int n_in,
                              void* d_out, int out_size)
{
    (void)in_sizes; (void)n_in; (void)out_size;
    const float* x   = (const float*)d_in[0];
    const float* mu  = (const float*)d_in[1];
    const float* wq  = (const float*)d_in[2];
    const float* wk  = (const float*)d_in[3];
    const float* wv  = (const float*)d_in[4];
    const float* wo  = (const float*)d_in[5];
    const float* wmq = (const float*)d_in[6];
    const float* wmk = (const float*)d_in[7];
    const float* wmv = (const float*)d_in[8];
    const float* qw  = (const float*)d_in[9];
    const float* kw  = (const float*)d_in[10];
    float* out = (float*)d_out;

    float *pq, *pk, *pv, *po;
    cudaGetSymbolAddress((void**)&pq, g_q);
    cudaGetSymbolAddress((void**)&pk, g_k);
    cudaGetSymbolAddress((void**)&pv, g_v);
    cudaGetSymbolAddress((void**)&po, g_o);

    const int gemm_smem = 4 * BUF_WORDS * 4;  // 73728 bytes
    cudaFuncSetAttribute(qkv_mma,   cudaFuncAttributeMaxDynamicSharedMemorySize, gemm_smem);
    cudaFuncSetAttribute(oproj_mma, cudaFuncAttributeMaxDynamicSharedMemorySize, gemm_smem);

    // Fused QKV projections on tensor cores (tf32), mu term folded as second K range
    qkv_mma<<<dim3(24, 16), 256, gemm_smem>>>(x, mu, wq, wmq, wk, wmk, wv, wmv, pq, pk, pv);

    // per-head RMSNorm + RoPE on q and k
    normrope_kernel<<<dim3(SEQ, NH + NKV), 128>>>(pq, pk, qw, kw);

    // causal GQA attention (fp32 CUDA-core flash)
    const size_t smem = (size_t)(2 * 64 * 129 + 64 * 128 + 64 * 65) * sizeof(float);
    cudaFuncSetAttribute(attn_kernel, cudaFuncAttributeMaxDynamicSharedMemorySize, (int)smem);
    attn_kernel<<<dim3(SEQ / 64, NH), 256, smem>>>(pq, pk, pv, po);

    // output projection on tensor cores (tf32)
    oproj_mma<<<dim3(16, 16), 256, gemm_smem>>>(po, wo, out);
}

// round 4
// speedup vs baseline: 3.4857x; 1.4318x over previous
#include <cuda_runtime.h>
#include <math.h>
#include <stdint.h>

#define SEQ 2048
#define HID 2048
#define NH 16
#define NKV 4
#define HD 128
#define QD (NH*HD)    /* 2048 */
#define KVD (NKV*HD)  /* 512  */

// Scratch (device globals: no allocations allowed)
__device__ float g_q[SEQ*QD];
__device__ float g_k[SEQ*KVD];
__device__ float g_v[SEQ*KVD];
__device__ float g_o[SEQ*QD];

// ---------------------------------------------------------------------------
// tf32 helpers (plain sm_80+ PTX — no sm_103a-gated instructions)
// ---------------------------------------------------------------------------
__device__ __forceinline__ uint32_t f2tf32(float x) {
    uint32_t r;
    asm("cvt.rna.tf32.f32 %0, %1;" : "=r"(r) : "f"(x));
    return r;
}

__device__ __forceinline__ void mma_tf32(float d[4], const uint32_t a[4], const uint32_t b[2]) {
    asm volatile(
        "mma.sync.aligned.m16n8k8.row.col.f32.tf32.tf32.f32 "
        "{%0,%1,%2,%3}, {%4,%5,%6,%7}, {%8,%9}, {%0,%1,%2,%3};"
        : "+f"(d[0]), "+f"(d[1]), "+f"(d[2]), "+f"(d[3])
        : "r"(a[0]), "r"(a[1]), "r"(a[2]), "r"(a[3]), "r"(b[0]), "r"(b[1]));
}

__device__ __forceinline__ void mma_tf32_u2(float d[4], const uint32_t a[4], uint2 b) {
    asm volatile(
        "mma.sync.aligned.m16n8k8.row.col.f32.tf32.tf32.f32 "
        "{%0,%1,%2,%3}, {%4,%5,%6,%7}, {%8,%9}, {%0,%1,%2,%3};"
        : "+f"(d[0]), "+f"(d[1]), "+f"(d[2]), "+f"(d[3])
        : "r"(a[0]), "r"(a[1]), "r"(a[2]), "r"(a[3]), "r"(b.x), "r"(b.y));
}

// ---------------------------------------------------------------------------
// Core tf32 MMA GEMM tile: C[128,128] = Ablk[128,K] @ Bblk[128,K]^T
// (+ A2blk @ B2blk^T when HAS_MU). 256 threads, BK=32, double-buffered SMEM.
// ---------------------------------------------------------------------------
#define BUF_WORDS (128 * 36)

template<bool HAS_MU>
__device__ __forceinline__ void gemm_core(
    const float* __restrict__ Ablk, const float* __restrict__ A2blk,
    const float* __restrict__ Bblk, const float* __restrict__ B2blk,
    float* __restrict__ Cblk, int ldc, int K, char* smem)
{
    uint32_t* s = (uint32_t*)smem;

    const int tid = threadIdx.x;
    const int wid = tid >> 5, lane = tid & 31;
    const int g = lane >> 2, t = lane & 3;
    const int m0 = (wid >> 2) * 64;
    const int n0 = (wid & 3) * 32;

    float acc[4][4][4];
#pragma unroll
    for (int i = 0; i < 4; ++i)
#pragma unroll
        for (int j = 0; j < 4; ++j)
#pragma unroll
            for (int q = 0; q < 4; ++q) acc[i][j][q] = 0.0f;

    const int nch = (HAS_MU ? 2 * K : K) >> 5;

    float4 pa[4], pb[4];
#pragma unroll
    for (int i = 0; i < 4; ++i) {
        int idx = tid + i * 256;
        int rr = idx >> 3, c4 = idx & 7;
        pa[i] = *(const float4*)(Ablk + (size_t)rr * K + c4 * 4);
        pb[i] = *(const float4*)(Bblk + (size_t)rr * K + c4 * 4);
    }

    for (int c = 0; c < nch; ++c) {
        const int buf = c & 1;
        uint32_t* sA = s + buf * (2 * BUF_WORDS);
        uint32_t* sB = sA + BUF_WORDS;

#pragma unroll
        for (int i = 0; i < 4; ++i) {
            int idx = tid + i * 256;
            int rr = idx >> 3, c4 = idx & 7;
            uint4 ua = make_uint4(f2tf32(pa[i].x), f2tf32(pa[i].y), f2tf32(pa[i].z), f2tf32(pa[i].w));
            uint4 ub = make_uint4(f2tf32(pb[i].x), f2tf32(pb[i].y), f2tf32(pb[i].z), f2tf32(pb[i].w));
            *(uint4*)(sA + rr * 36 + c4 * 4) = ua;
            *(uint4*)(sB + rr * 36 + c4 * 4) = ub;
        }
        __syncthreads();

        if (c + 1 < nch) {
            int kk = (c + 1) << 5;
            const float* Ap = Ablk; const float* Bp = Bblk;
            if (HAS_MU && kk >= K) { Ap = A2blk; Bp = B2blk; kk -= K; }
#pragma unroll
            for (int i = 0; i < 4; ++i) {
                int idx = tid + i * 256;
                int rr = idx >> 3, c4 = idx & 7;
                pa[i] = *(const float4*)(Ap + (size_t)rr * K + kk + c4 * 4);
                pb[i] = *(const float4*)(Bp + (size_t)rr * K + kk + c4 * 4);
            }
        }

#pragma unroll
        for (int ks = 0; ks < 4; ++ks) {
            uint32_t af[4][4], bf[4][2];
#pragma unroll
            for (int mt = 0; mt < 4; ++mt) {
                int mr = m0 + mt * 16 + g;
                af[mt][0] = sA[mr * 36 + ks * 8 + t];
                af[mt][1] = sA[(mr + 8) * 36 + ks * 8 + t];
                af[mt][2] = sA[mr * 36 + ks * 8 + t + 4];
                af[mt][3] = sA[(mr + 8) * 36 + ks * 8 + t + 4];
            }
#pragma unroll
            for (int nt = 0; nt < 4; ++nt) {
                int nr = n0 + nt * 8 + g;
                bf[nt][0] = sB[nr * 36 + ks * 8 + t];
                bf[nt][1] = sB[nr * 36 + ks * 8 + t + 4];
            }
#pragma unroll
            for (int mt = 0; mt < 4; ++mt)
#pragma unroll
                for (int nt = 0; nt < 4; ++nt)
                    mma_tf32(acc[mt][nt], af[mt], bf[nt]);
        }
        __syncthreads();
    }

#pragma unroll
    for (int mt = 0; mt < 4; ++mt) {
        int r0 = m0 + mt * 16 + g;
#pragma unroll
        for (int nt = 0; nt < 4; ++nt) {
            int cc = n0 + nt * 8 + 2 * t;
            *(float2*)(Cblk + (size_t)r0 * ldc + cc)       = make_float2(acc[mt][nt][0], acc[mt][nt][1]);
            *(float2*)(Cblk + (size_t)(r0 + 8) * ldc + cc) = make_float2(acc[mt][nt][2], acc[mt][nt][3]);
        }
    }
}

// Fused QKV projection: grid = (24, 16). Col blocks 0..15 -> Q, 16..19 -> K, 20..23 -> V.
__global__ __launch_bounds__(256) void qkv_mma(
    const float* __restrict__ x, const float* __restrict__ mu,
    const float* __restrict__ wq, const float* __restrict__ wmq,
    const float* __restrict__ wk, const float* __restrict__ wmk,
    const float* __restrict__ wv, const float* __restrict__ wmv,
    float* __restrict__ pq, float* __restrict__ pk, float* __restrict__ pv)
{
    extern __shared__ char smem[];
    const int cb = blockIdx.x;
    const int row0 = blockIdx.y * 128;

    const float *B, *B2; float* C; int ldc, ccol;
    if (cb < 16)      { B = wq; B2 = wmq; C = pq; ldc = QD;  ccol = cb * 128; }
    else if (cb < 20) { B = wk; B2 = wmk; C = pk; ldc = KVD; ccol = (cb - 16) * 128; }
    else              { B = wv; B2 = wmv; C = pv; ldc = KVD; ccol = (cb - 20) * 128; }

    gemm_core<true>(x + (size_t)row0 * HID, mu + (size_t)row0 * HID,
                    B + (size_t)ccol * HID, B2 + (size_t)ccol * HID,
                    C + (size_t)row0 * ldc + ccol, ldc, HID, smem);
}

// Output projection: grid = (16, 16)
__global__ __launch_bounds__(256) void oproj_mma(
    const float* __restrict__ A, const float* __restrict__ B, float* __restrict__ C)
{
    extern __shared__ char smem[];
    const int row0 = blockIdx.y * 128;
    const int ccol = blockIdx.x * 128;
    gemm_core<false>(A + (size_t)row0 * QD, nullptr,
                     B + (size_t)ccol * QD, nullptr,
                     C + (size_t)row0 * QD + ccol, QD, QD, smem);
}

// ---------------------------------------------------------------------------
// Per-head RMSNorm + RoPE (in place on g_q / g_k). grid=(SEQ, NH+NKV), 128 thr
// ---------------------------------------------------------------------------
__global__ __launch_bounds__(128) void normrope_kernel(
    float* __restrict__ qb, float* __restrict__ kb,
    const float* __restrict__ qw, const float* __restrict__ kw)
{
    const int pos = blockIdx.x;
    const int hh = blockIdx.y;
    const int d = threadIdx.x;

    float* buf; int stride, col0; const float* w;
    if (hh < NH) { buf = qb; stride = QD;  col0 = hh * HD;        w = qw; }
    else         { buf = kb; stride = KVD; col0 = (hh - NH) * HD; w = kw; }

    const size_t idx = (size_t)pos * stride + col0 + d;
    float x = buf[idx];

    float ss = x * x;
#pragma unroll
    for (int off = 16; off; off >>= 1) ss += __shfl_xor_sync(0xffffffffu, ss, off);

    __shared__ float red[4];
    __shared__ float xs[128];
    if ((d & 31) == 0) red[d >> 5] = ss;
    __syncthreads();
    ss = red[0] + red[1] + red[2] + red[3];

    float xn = x * rsqrtf(ss * (1.0f / 128.0f) + 1e-6f) * w[d];
    xs[d] = xn;
    __syncthreads();
    float rot = (d < 64) ? -xs[d + 64] : xs[d - 64];

    float fi = (float)(d & 63);
    float ang = (float)pos * powf(10000.0f, -fi * (1.0f / 64.0f));
    float sn, cs;
    sincosf(ang, &sn, &cs);
    buf[idx] = xn * cs + rot * sn;
}

// ---------------------------------------------------------------------------
// Tensor-core causal flash attention (tf32 mma).
// Q-tile 128 rows, KV-tile 64. 8 warps (256 thr). grid = (SEQ/128, NH).
// SMEM word layout (uint32):
//   K  [64][136]  at 0        (fragment-permuted k-dim)
//   Vt [128][72]  at 8704     (V transposed, permuted)
//   P  [128][72]  at 17920
//   Q staging [128][136] at 0 (overlaps K+V; consumed before K/V writes)
// perm(k) within row: (k>>3)*8 + (k&3)*2 + ((k>>2)&1)  -> (t, t+4) adjacent
// ---------------------------------------------------------------------------
#define ATTN_SMEM_WORDS 27136

__global__ __launch_bounds__(256, 1) void attn_mma(
    const float* __restrict__ q, const float* __restrict__ k,
    const float* __restrict__ v, float* __restrict__ o)
{
    extern __shared__ uint32_t sw[];
    uint32_t* sK = sw;            // [64][136]
    uint32_t* sV = sw + 8704;     // [128][72]
    uint32_t* sP = sw + 17920;    // [128][72]
    uint32_t* sQ = sw;            // staging [128][136]

    const int qt = blockIdx.x;
    const int h = blockIdx.y;
    const int kvh = h >> 2;
    const int qrow0 = qt * 128;
    const int tid = threadIdx.x;
    const int w = tid >> 5, lane = tid & 31;
    const int gg = lane >> 2, t = lane & 3;
    const int m0 = w * 16;

    // ---- stage Q tile into permuted smem (coalesced) ----
#pragma unroll
    for (int i = 0; i < 16; ++i) {
        int id = tid + i * 256;          // 0..4095 over 128 rows x 32 float4
        int r = id >> 5, c4 = id & 31, c = c4 * 4;
        float4 val = *(const float4*)(q + (size_t)(qrow0 + r) * QD + h * HD + c);
        uint32_t base = (uint32_t)(r * 136 + (c >> 3) * 8 + ((c >> 2) & 1));
        sQ[base + 0] = f2tf32(val.x);
        sQ[base + 2] = f2tf32(val.y);
        sQ[base + 4] = f2tf32(val.z);
        sQ[base + 6] = f2tf32(val.w);
    }
    __syncthreads();

    // ---- load Q fragments into registers (held across whole kv loop) ----
    uint32_t qf[16][4];
#pragma unroll
    for (int ks = 0; ks < 16; ++ks) {
        uint2 q0 = *(const uint2*)&sQ[(m0 + gg) * 136 + ks * 8 + 2 * t];
        uint2 q1 = *(const uint2*)&sQ[(m0 + gg + 8) * 136 + ks * 8 + 2 * t];
        qf[ks][0] = q0.x; qf[ks][1] = q1.x; qf[ks][2] = q0.y; qf[ks][3] = q1.y;
    }
    __syncthreads();

    float oacc[16][4];
#pragma unroll
    for (int i = 0; i < 16; ++i)
#pragma unroll
        for (int j = 0; j < 4; ++j) oacc[i][j] = 0.0f;
    float mrow0 = -1e30f, mrow1 = -1e30f, lrow0 = 0.0f, lrow1 = 0.0f;

    const float scale = 0.08838834764831845f;  // 1/sqrt(128)
    const int jmax = 2 * qt + 2;
    const bool active_base_known = true; (void)active_base_known;

    for (int jt = 0; jt < jmax; ++jt) {
        if (jt) __syncthreads();

        // ---- load K tile (coalesced gmem; c varies per lane) ----
#pragma unroll
        for (int i = 0; i < 8; ++i) {
            int id = tid + i * 256;      // 0..2047 over 64 rows x 32 float4
            int r = id >> 5, c4 = id & 31, c = c4 * 4;
            float4 kv = *(const float4*)(k + (size_t)(jt * 64 + r) * KVD + kvh * HD + c);
            uint32_t kb = (uint32_t)(r * 136 + (c >> 3) * 8 + ((c >> 2) & 1));
            sK[kb + 0] = f2tf32(kv.x);
            sK[kb + 2] = f2tf32(kv.y);
            sK[kb + 4] = f2tf32(kv.z);
            sK[kb + 6] = f2tf32(kv.w);
        }
        // ---- load V tile transposed (r varies per lane -> conflict-free STS) ----
#pragma unroll
        for (int i = 0; i < 8; ++i) {
            int id = tid + i * 256;
            int r = id & 63, c4 = id >> 6, c = c4 * 4;
            float4 vv = *(const float4*)(v + (size_t)(jt * 64 + r) * KVD + kvh * HD + c);
            uint32_t rp = (uint32_t)((r >> 3) * 8 + (r & 3) * 2 + ((r >> 2) & 1));
            sV[(c + 0) * 72 + rp] = f2tf32(vv.x);
            sV[(c + 1) * 72 + rp] = f2tf32(vv.y);
            sV[(c + 2) * 72 + rp] = f2tf32(vv.z);
            sV[(c + 3) * 72 + rp] = f2tf32(vv.w);
        }
        __syncthreads();

        // warp fully above the causal boundary? skip compute
        const bool active = (jt * 64 <= qrow0 + m0 + 15);
        if (active) {
            // ---- S = Q @ K^T ----
            float sacc[8][4];
#pragma unroll
            for (int i = 0; i < 8; ++i)
#pragma unroll
                for (int j = 0; j < 4; ++j) sacc[i][j] = 0.0f;

#pragma unroll
            for (int ks = 0; ks < 16; ++ks) {
#pragma unroll
                for (int nt = 0; nt < 8; ++nt) {
                    uint2 b = *(const uint2*)&sK[(nt * 8 + gg) * 136 + ks * 8 + 2 * t];
                    mma_tf32_u2(sacc[nt], qf[ks], b);
                }
            }

            // ---- scale + mask + online softmax ----
            const int r0 = qrow0 + m0 + gg;
            const int r1 = r0 + 8;
            const bool edge = (jt >= 2 * qt);
            float rm0 = -1e30f, rm1 = -1e30f;
#pragma unroll
            for (int nt = 0; nt < 8; ++nt) {
                float c0 = sacc[nt][0] * scale, c1 = sacc[nt][1] * scale;
                float c2 = sacc[nt][2] * scale, c3 = sacc[nt][3] * scale;
                if (edge) {
                    int colb = jt * 64 + nt * 8 + 2 * t;
                    if (colb     > r0) c0 = -1e30f;
                    if (colb + 1 > r0) c1 = -1e30f;
                    if (colb     > r1) c2 = -1e30f;
                    if (colb + 1 > r1) c3 = -1e30f;
                }
                sacc[nt][0] = c0; sacc[nt][1] = c1; sacc[nt][2] = c2; sacc[nt][3] = c3;
                rm0 = fmaxf(rm0, fmaxf(c0, c1));
                rm1 = fmaxf(rm1, fmaxf(c2, c3));
            }
            rm0 = fmaxf(rm0, __shfl_xor_sync(0xffffffffu, rm0, 1));
            rm0 = fmaxf(rm0, __shfl_xor_sync(0xffffffffu, rm0, 2));
            rm1 = fmaxf(rm1, __shfl_xor_sync(0xffffffffu, rm1, 1));
            rm1 = fmaxf(rm1, __shfl_xor_sync(0xffffffffu, rm1, 2));

            float mn0 = fmaxf(mrow0, rm0), mn1 = fmaxf(mrow1, rm1);
            float al0 = __expf(mrow0 - mn0), al1 = __expf(mrow1 - mn1);
            mrow0 = mn0; mrow1 = mn1;

            // P store offsets: col 2t -> word A(t), col 2t+1 -> +2
            const uint32_t pA = (uint32_t)(((2 * t) & 3) * 2 + ((t >> 1) & 1));
            const uint32_t pb0 = (uint32_t)((m0 + gg) * 72) + pA;
            const uint32_t pb1 = pb0 + 8 * 72;
            float rs0 = 0.0f, rs1 = 0.0f;
#pragma unroll
            for (int nt = 0; nt < 8; ++nt) {
                float p0 = __expf(sacc[nt][0] - mn0);
                float p1 = __expf(sacc[nt][1] - mn0);
                float p2 = __expf(sacc[nt][2] - mn1);
                float p3 = __expf(sacc[nt][3] - mn1);
                rs0 += p0 + p1; rs1 += p2 + p3;
                sP[pb0 + nt * 8]     = f2tf32(p0);
                sP[pb0 + nt * 8 + 2] = f2tf32(p1);
                sP[pb1 + nt * 8]     = f2tf32(p2);
                sP[pb1 + nt * 8 + 2] = f2tf32(p3);
            }
            rs0 += __shfl_xor_sync(0xffffffffu, rs0, 1);
            rs0 += __shfl_xor_sync(0xffffffffu, rs0, 2);
            rs1 += __shfl_xor_sync(0xffffffffu, rs1, 1);
            rs1 += __shfl_xor_sync(0xffffffffu, rs1, 2);
            lrow0 = lrow0 * al0 + rs0;
            lrow1 = lrow1 * al1 + rs1;

#pragma unroll
            for (int nt = 0; nt < 16; ++nt) {
                oacc[nt][0] *= al0; oacc[nt][1] *= al0;
                oacc[nt][2] *= al1; oacc[nt][3] *= al1;
            }
            __syncwarp();

            // ---- O += P @ V ----
#pragma unroll
            for (int ks = 0; ks < 8; ++ks) {
                uint2 pa0 = *(const uint2*)&sP[(m0 + gg) * 72 + ks * 8 + 2 * t];
                uint2 pa1 = *(const uint2*)&sP[(m0 + gg + 8) * 72 + ks * 8 + 2 * t];
                uint32_t a[4] = {pa0.x, pa1.x, pa0.y, pa1.y};
#pragma unroll
                for (int nt = 0; nt < 16; ++nt) {
                    uint2 b = *(const uint2*)&sV[(nt * 8 + gg) * 72 + ks * 8 + 2 * t];
                    mma_tf32_u2(oacc[nt], a, b);
                }
            }
        }
    }

    // ---- normalize + write ----
    const float inv0 = 1.0f / lrow0, inv1 = 1.0f / lrow1;
    const int r0 = qrow0 + m0 + gg;
#pragma unroll
    for (int nt = 0; nt < 16; ++nt) {
        int cc = h * HD + nt * 8 + 2 * t;
        *(float2*)(o + (size_t)r0 * QD + cc) =
            make_float2(oacc[nt][0] * inv0, oacc[nt][1] * inv0);
        *(float2*)(o + (size_t)(r0 + 8) * QD + cc) =
            make_float2(oacc[nt][2] * inv1, oacc[nt][3] * inv1);
    }
}

// ---------------------------------------------------------------------------
extern "C" void kernel_launch(void* const* d_in, const int* in_sizes, int n_in,
                              void* d_out, int out_size)
{
    (void)in_sizes; (void)n_in; (void)out_size;
    const float* x   = (const float*)d_in[0];
    const float* mu  = (const float*)d_in[1];
    const float* wq  = (const float*)d_in[2];
    const float* wk  = (const float*)d_in[3];
    const float* wv  = (const float*)d_in[4];
    const float* wo  = (const float*)d_in[5];
    const float* wmq = (const float*)d_in[6];
    const float* wmk = (const float*)d_in[7];
    const float* wmv = (const float*)d_in[8];
    const float* qw  = (const float*)d_in[9];
    const float* kw  = (const float*)d_in[10];
    float* out = (float*)d_out;

    float *pq, *pk, *pv, *po;
    cudaGetSymbolAddress((void**)&pq, g_q);
    cudaGetSymbolAddress((void**)&pk, g_k);
    cudaGetSymbolAddress((void**)&pv, g_v);
    cudaGetSymbolAddress((void**)&po, g_o);

    const int gemm_smem = 4 * BUF_WORDS * 4;  // 73728 bytes
    cudaFuncSetAttribute(qkv_mma,   cudaFuncAttributeMaxDynamicSharedMemorySize, gemm_smem);
    cudaFuncSetAttribute(oproj_mma, cudaFuncAttributeMaxDynamicSharedMemorySize, gemm_smem);

    // Fused QKV projections on tensor cores (tf32), mu term folded as second K range
    qkv_mma<<<dim3(24, 16), 256, gemm_smem>>>(x, mu, wq, wmq, wk, wmk, wv, wmv, pq, pk, pv);

    // per-head RMSNorm + RoPE on q and k
    normrope_kernel<<<dim3(SEQ, NH + NKV), 128>>>(pq, pk, qw, kw);

    // causal GQA attention on tensor cores (tf32)
    const int attn_smem = ATTN_SMEM_WORDS * 4;  // 108544 bytes
    cudaFuncSetAttribute(attn_mma, cudaFuncAttributeMaxDynamicSharedMemorySize, attn_smem);
    attn_mma<<<dim3(SEQ / 128, NH), 256, attn_smem>>>(pq, pk, pv, po);

    // output projection on tensor cores (tf32)
    oproj_mma<<<dim3(16, 16), 256, gemm_smem>>>(po, wo, out);
}

// round 5
// speedup vs baseline: 3.7688x; 1.0812x over previous
#include <cuda_runtime.h>
#include <math.h>
#include <stdint.h>

#define SEQ 2048
#define HID 2048
#define NH 16
#define NKV 4
#define HD 128
#define QD (NH*HD)    /* 2048 */
#define KVD (NKV*HD)  /* 512  */

// Scratch (device globals: no allocations allowed)
__device__ float g_q[SEQ*QD];
__device__ float g_k[SEQ*KVD];
__device__ float g_v[SEQ*KVD];
__device__ float g_o[SEQ*QD];

// ---------------------------------------------------------------------------
// tf32 helpers (plain sm_80+ PTX — no sm_103a-gated instructions)
// ---------------------------------------------------------------------------
__device__ __forceinline__ uint32_t f2tf32(float x) {
    uint32_t r;
    asm("cvt.rna.tf32.f32 %0, %1;" : "=r"(r) : "f"(x));
    return r;
}

__device__ __forceinline__ void mma_tf32(float d[4], const uint32_t a[4], const uint32_t b[2]) {
    asm volatile(
        "mma.sync.aligned.m16n8k8.row.col.f32.tf32.tf32.f32 "
        "{%0,%1,%2,%3}, {%4,%5,%6,%7}, {%8,%9}, {%0,%1,%2,%3};"
        : "+f"(d[0]), "+f"(d[1]), "+f"(d[2]), "+f"(d[3])
        : "r"(a[0]), "r"(a[1]), "r"(a[2]), "r"(a[3]), "r"(b[0]), "r"(b[1]));
}

__device__ __forceinline__ void mma_tf32_u2(float d[4], const uint32_t a[4], uint2 b) {
    asm volatile(
        "mma.sync.aligned.m16n8k8.row.col.f32.tf32.tf32.f32 "
        "{%0,%1,%2,%3}, {%4,%5,%6,%7}, {%8,%9}, {%0,%1,%2,%3};"
        : "+f"(d[0]), "+f"(d[1]), "+f"(d[2]), "+f"(d[3])
        : "r"(a[0]), "r"(a[1]), "r"(a[2]), "r"(a[3]), "r"(b.x), "r"(b.y));
}

// ---------------------------------------------------------------------------
// Core tf32 MMA GEMM tile: C[128,128] = Ablk[128,K] @ Bblk[128,K]^T
// (+ A2blk @ B2blk^T when HAS_MU). 256 threads, BK=32, double-buffered SMEM,
// ONE barrier per chunk (store[i] -> sync -> mma[i] is hazard-free: a warp
// reaches store[i+2] on buffer i%2 only after all warps passed sync at i+1,
// which implies their mma[i] already completed).
// Designed for 2 CTAs/SM: cross-CTA ping-pong hides the exposed load latency.
// ---------------------------------------------------------------------------
#define BUF_WORDS (128 * 36)

template<bool HAS_MU>
__device__ __forceinline__ void gemm_core(
    const float* __restrict__ Ablk, const float* __restrict__ A2blk,
    const float* __restrict__ Bblk, const float* __restrict__ B2blk,
    float* __restrict__ Cblk, int ldc, int K, char* smem)
{
    uint32_t* s = (uint32_t*)smem;

    const int tid = threadIdx.x;
    const int wid = tid >> 5, lane = tid & 31;
    const int g = lane >> 2, t = lane & 3;
    const int m0 = (wid >> 2) * 64;
    const int n0 = (wid & 3) * 32;

    const int lrow = tid >> 3;          // 0..31 -> row group (x4 rows)... see below
    (void)lrow;

    float acc[4][4][4];
#pragma unroll
    for (int i = 0; i < 4; ++i)
#pragma unroll
        for (int j = 0; j < 4; ++j)
#pragma unroll
            for (int q = 0; q < 4; ++q) acc[i][j][q] = 0.0f;

    const int nch = (HAS_MU ? 2 * K : K) >> 5;

    for (int c = 0; c < nch; ++c) {
        int kk = c << 5;
        const float* Ap = Ablk; const float* Bp = Bblk;
        if (HAS_MU && kk >= K) { Ap = A2blk; Bp = B2blk; kk -= K; }

        uint32_t* sA = s + (c & 1) * (2 * BUF_WORDS);
        uint32_t* sB = sA + BUF_WORDS;

        // JIT load -> cvt -> store (temps are short-lived; no prefetch regs)
#pragma unroll
        for (int i = 0; i < 4; ++i) {
            int idx = tid + i * 256;
            int rr = idx >> 3, c4 = idx & 7;
            float4 av = *(const float4*)(Ap + (size_t)rr * K + kk + c4 * 4);
            float4 bv = *(const float4*)(Bp + (size_t)rr * K + kk + c4 * 4);
            uint4 ua = make_uint4(f2tf32(av.x), f2tf32(av.y), f2tf32(av.z), f2tf32(av.w));
            uint4 ub = make_uint4(f2tf32(bv.x), f2tf32(bv.y), f2tf32(bv.z), f2tf32(bv.w));
            *(uint4*)(sA + rr * 36 + c4 * 4) = ua;
            *(uint4*)(sB + rr * 36 + c4 * 4) = ub;
        }
        __syncthreads();

#pragma unroll
        for (int ks = 0; ks < 4; ++ks) {
            uint32_t af[4][4], bf[4][2];
#pragma unroll
            for (int mt = 0; mt < 4; ++mt) {
                int mr = m0 + mt * 16 + g;
                af[mt][0] = sA[mr * 36 + ks * 8 + t];
                af[mt][1] = sA[(mr + 8) * 36 + ks * 8 + t];
                af[mt][2] = sA[mr * 36 + ks * 8 + t + 4];
                af[mt][3] = sA[(mr + 8) * 36 + ks * 8 + t + 4];
            }
#pragma unroll
            for (int nt = 0; nt < 4; ++nt) {
                int nr = n0 + nt * 8 + g;
                bf[nt][0] = sB[nr * 36 + ks * 8 + t];
                bf[nt][1] = sB[nr * 36 + ks * 8 + t + 4];
            }
#pragma unroll
            for (int mt = 0; mt < 4; ++mt)
#pragma unroll
                for (int nt = 0; nt < 4; ++nt)
                    mma_tf32(acc[mt][nt], af[mt], bf[nt]);
        }
    }

#pragma unroll
    for (int mt = 0; mt < 4; ++mt) {
        int r0 = m0 + mt * 16 + g;
#pragma unroll
        for (int nt = 0; nt < 4; ++nt) {
            int cc = n0 + nt * 8 + 2 * t;
            *(float2*)(Cblk + (size_t)r0 * ldc + cc)       = make_float2(acc[mt][nt][0], acc[mt][nt][1]);
            *(float2*)(Cblk + (size_t)(r0 + 8) * ldc + cc) = make_float2(acc[mt][nt][2], acc[mt][nt][3]);
        }
    }
}

// Fused QKV projection: grid = (24, 16). Col blocks 0..15 -> Q, 16..19 -> K, 20..23 -> V.
__global__ __launch_bounds__(256, 2) void qkv_mma(
    const float* __restrict__ x, const float* __restrict__ mu,
    const float* __restrict__ wq, const float* __restrict__ wmq,
    const float* __restrict__ wk, const float* __restrict__ wmk,
    const float* __restrict__ wv, const float* __restrict__ wmv,
    float* __restrict__ pq, float* __restrict__ pk, float* __restrict__ pv)
{
    extern __shared__ char smem[];
    const int cb = blockIdx.x;
    const int row0 = blockIdx.y * 128;

    const float *B, *B2; float* C; int ldc, ccol;
    if (cb < 16)      { B = wq; B2 = wmq; C = pq; ldc = QD;  ccol = cb * 128; }
    else if (cb < 20) { B = wk; B2 = wmk; C = pk; ldc = KVD; ccol = (cb - 16) * 128; }
    else              { B = wv; B2 = wmv; C = pv; ldc = KVD; ccol = (cb - 20) * 128; }

    gemm_core<true>(x + (size_t)row0 * HID, mu + (size_t)row0 * HID,
                    B + (size_t)ccol * HID, B2 + (size_t)ccol * HID,
                    C + (size_t)row0 * ldc + ccol, ldc, HID, smem);
}

// Output projection: grid = (16, 16)
__global__ __launch_bounds__(256, 2) void oproj_mma(
    const float* __restrict__ A, const float* __restrict__ B, float* __restrict__ C)
{
    extern __shared__ char smem[];
    const int row0 = blockIdx.y * 128;
    const int ccol = blockIdx.x * 128;
    gemm_core<false>(A + (size_t)row0 * QD, nullptr,
                     B + (size_t)ccol * QD, nullptr,
                     C + (size_t)row0 * QD + ccol, QD, QD, smem);
}

// ---------------------------------------------------------------------------
// Per-head RMSNorm + RoPE (in place on g_q / g_k). grid=(SEQ, NH+NKV), 128 thr
// ---------------------------------------------------------------------------
__global__ __launch_bounds__(128) void normrope_kernel(
    float* __restrict__ qb, float* __restrict__ kb,
    const float* __restrict__ qw, const float* __restrict__ kw)
{
    const int pos = blockIdx.x;
    const int hh = blockIdx.y;
    const int d = threadIdx.x;

    float* buf; int stride, col0; const float* w;
    if (hh < NH) { buf = qb; stride = QD;  col0 = hh * HD;        w = qw; }
    else         { buf = kb; stride = KVD; col0 = (hh - NH) * HD; w = kw; }

    const size_t idx = (size_t)pos * stride + col0 + d;
    float x = buf[idx];

    float ss = x * x;
#pragma unroll
    for (int off = 16; off; off >>= 1) ss += __shfl_xor_sync(0xffffffffu, ss, off);

    __shared__ float red[4];
    __shared__ float xs[128];
    if ((d & 31) == 0) red[d >> 5] = ss;
    __syncthreads();
    ss = red[0] + red[1] + red[2] + red[3];

    float xn = x * rsqrtf(ss * (1.0f / 128.0f) + 1e-6f) * w[d];
    xs[d] = xn;
    __syncthreads();
    float rot = (d < 64) ? -xs[d + 64] : xs[d - 64];

    float fi = (float)(d & 63);
    float ang = (float)pos * powf(10000.0f, -fi * (1.0f / 64.0f));
    float sn, cs;
    sincosf(ang, &sn, &cs);
    buf[idx] = xn * cs + rot * sn;
}

// ---------------------------------------------------------------------------
// Tensor-core causal flash attention (tf32 mma).
// Q-tile 128 rows, KV-tile 64. 8 warps (256 thr). grid = (SEQ/128, NH).
// blockIdx.x is REVERSED onto qt so heavy diagonal tiles launch first.
// ---------------------------------------------------------------------------
#define ATTN_SMEM_WORDS 27136

__global__ __launch_bounds__(256, 1) void attn_mma(
    const float* __restrict__ q, const float* __restrict__ k,
    const float* __restrict__ v, float* __restrict__ o)
{
    extern __shared__ uint32_t sw[];
    uint32_t* sK = sw;            // [64][136]
    uint32_t* sV = sw + 8704;     // [128][72]
    uint32_t* sP = sw + 17920;    // [128][72]
    uint32_t* sQ = sw;            // staging [128][136] (overlaps K+V)

    const int qt = gridDim.x - 1 - blockIdx.x;   // heavy tiles first
    const int h = blockIdx.y;
    const int kvh = h >> 2;
    const int qrow0 = qt * 128;
    const int tid = threadIdx.x;
    const int w = tid >> 5, lane = tid & 31;
    const int gg = lane >> 2, t = lane & 3;
    const int m0 = w * 16;

    // ---- stage Q tile into permuted smem (coalesced) ----
#pragma unroll
    for (int i = 0; i < 16; ++i) {
        int id = tid + i * 256;
        int r = id >> 5, c4 = id & 31, c = c4 * 4;
        float4 val = *(const float4*)(q + (size_t)(qrow0 + r) * QD + h * HD + c);
        uint32_t base = (uint32_t)(r * 136 + (c >> 3) * 8 + ((c >> 2) & 1));
        sQ[base + 0] = f2tf32(val.x);
        sQ[base + 2] = f2tf32(val.y);
        sQ[base + 4] = f2tf32(val.z);
        sQ[base + 6] = f2tf32(val.w);
    }
    __syncthreads();

    // ---- load Q fragments into registers ----
    uint32_t qf[16][4];
#pragma unroll
    for (int ks = 0; ks < 16; ++ks) {
        uint2 q0 = *(const uint2*)&sQ[(m0 + gg) * 136 + ks * 8 + 2 * t];
        uint2 q1 = *(const uint2*)&sQ[(m0 + gg + 8) * 136 + ks * 8 + 2 * t];
        qf[ks][0] = q0.x; qf[ks][1] = q1.x; qf[ks][2] = q0.y; qf[ks][3] = q1.y;
    }
    __syncthreads();

    float oacc[16][4];
#pragma unroll
    for (int i = 0; i < 16; ++i)
#pragma unroll
        for (int j = 0; j < 4; ++j) oacc[i][j] = 0.0f;
    float mrow0 = -1e30f, mrow1 = -1e30f, lrow0 = 0.0f, lrow1 = 0.0f;

    const float scale = 0.08838834764831845f;  // 1/sqrt(128)
    const int jmax = 2 * qt + 2;

    for (int jt = 0; jt < jmax; ++jt) {
        if (jt) __syncthreads();

        // ---- load K tile ----
#pragma unroll
        for (int i = 0; i < 8; ++i) {
            int id = tid + i * 256;
            int r = id >> 5, c4 = id & 31, c = c4 * 4;
            float4 kv = *(const float4*)(k + (size_t)(jt * 64 + r) * KVD + kvh * HD + c);
            uint32_t kb = (uint32_t)(r * 136 + (c >> 3) * 8 + ((c >> 2) & 1));
            sK[kb + 0] = f2tf32(kv.x);
            sK[kb + 2] = f2tf32(kv.y);
            sK[kb + 4] = f2tf32(kv.z);
            sK[kb + 6] = f2tf32(kv.w);
        }
        // ---- load V tile transposed ----
#pragma unroll
        for (int i = 0; i < 8; ++i) {
            int id = tid + i * 256;
            int r = id & 63, c4 = id >> 6, c = c4 * 4;
            float4 vv = *(const float4*)(v + (size_t)(jt * 64 + r) * KVD + kvh * HD + c);
            uint32_t rp = (uint32_t)((r >> 3) * 8 + (r & 3) * 2 + ((r >> 2) & 1));
            sV[(c + 0) * 72 + rp] = f2tf32(vv.x);
            sV[(c + 1) * 72 + rp] = f2tf32(vv.y);
            sV[(c + 2) * 72 + rp] = f2tf32(vv.z);
            sV[(c + 3) * 72 + rp] = f2tf32(vv.w);
        }
        __syncthreads();

        const bool active = (jt * 64 <= qrow0 + m0 + 15);
        if (active) {
            // ---- S = Q @ K^T ----
            float sacc[8][4];
#pragma unroll
            for (int i = 0; i < 8; ++i)
#pragma unroll
                for (int j = 0; j < 4; ++j) sacc[i][j] = 0.0f;

#pragma unroll
            for (int ks = 0; ks < 16; ++ks) {
#pragma unroll
                for (int nt = 0; nt < 8; ++nt) {
                    uint2 b = *(const uint2*)&sK[(nt * 8 + gg) * 136 + ks * 8 + 2 * t];
                    mma_tf32_u2(sacc[nt], qf[ks], b);
                }
            }

            // ---- scale + mask + online softmax ----
            const int r0 = qrow0 + m0 + gg;
            const int r1 = r0 + 8;
            const bool edge = (jt >= 2 * qt);
            float rm0 = -1e30f, rm1 = -1e30f;
#pragma unroll
            for (int nt = 0; nt < 8; ++nt) {
                float c0 = sacc[nt][0] * scale, c1 = sacc[nt][1] * scale;
                float c2 = sacc[nt][2] * scale, c3 = sacc[nt][3] * scale;
                if (edge) {
                    int colb = jt * 64 + nt * 8 + 2 * t;
                    if (colb     > r0) c0 = -1e30f;
                    if (colb + 1 > r0) c1 = -1e30f;
                    if (colb     > r1) c2 = -1e30f;
                    if (colb + 1 > r1) c3 = -1e30f;
                }
                sacc[nt][0] = c0; sacc[nt][1] = c1; sacc[nt][2] = c2; sacc[nt][3] = c3;
                rm0 = fmaxf(rm0, fmaxf(c0, c1));
                rm1 = fmaxf(rm1, fmaxf(c2, c3));
            }
            rm0 = fmaxf(rm0, __shfl_xor_sync(0xffffffffu, rm0, 1));
            rm0 = fmaxf(rm0, __shfl_xor_sync(0xffffffffu, rm0, 2));
            rm1 = fmaxf(rm1, __shfl_xor_sync(0xffffffffu, rm1, 1));
            rm1 = fmaxf(rm1, __shfl_xor_sync(0xffffffffu, rm1, 2));

            float mn0 = fmaxf(mrow0, rm0), mn1 = fmaxf(mrow1, rm1);
            float al0 = __expf(mrow0 - mn0), al1 = __expf(mrow1 - mn1);
            mrow0 = mn0; mrow1 = mn1;

            const uint32_t pA = (uint32_t)(((2 * t) & 3) * 2 + ((t >> 1) & 1));
            const uint32_t pb0 = (uint32_t)((m0 + gg) * 72) + pA;
            const uint32_t pb1 = pb0 + 8 * 72;
            float rs0 = 0.0f, rs1 = 0.0f;
#pragma unroll
            for (int nt = 0; nt < 8; ++nt) {
                float p0 = __expf(sacc[nt][0] - mn0);
                float p1 = __expf(sacc[nt][1] - mn0);
                float p2 = __expf(sacc[nt][2] - mn1);
                float p3 = __expf(sacc[nt][3] - mn1);
                rs0 += p0 + p1; rs1 += p2 + p3;
                sP[pb0 + nt * 8]     = f2tf32(p0);
                sP[pb0 + nt * 8 + 2] = f2tf32(p1);
                sP[pb1 + nt * 8]     = f2tf32(p2);
                sP[pb1 + nt * 8 + 2] = f2tf32(p3);
            }
            rs0 += __shfl_xor_sync(0xffffffffu, rs0, 1);
            rs0 += __shfl_xor_sync(0xffffffffu, rs0, 2);
            rs1 += __shfl_xor_sync(0xffffffffu, rs1, 1);
            rs1 += __shfl_xor_sync(0xffffffffu, rs1, 2);
            lrow0 = lrow0 * al0 + rs0;
            lrow1 = lrow1 * al1 + rs1;

#pragma unroll
            for (int nt = 0; nt < 16; ++nt) {
                oacc[nt][0] *= al0; oacc[nt][1] *= al0;
                oacc[nt][2] *= al1; oacc[nt][3] *= al1;
            }
            __syncwarp();

            // ---- O += P @ V ----
#pragma unroll
            for (int ks = 0; ks < 8; ++ks) {
                uint2 pa0 = *(const uint2*)&sP[(m0 + gg) * 72 + ks * 8 + 2 * t];
                uint2 pa1 = *(const uint2*)&sP[(m0 + gg + 8) * 72 + ks * 8 + 2 * t];
                uint32_t a[4] = {pa0.x, pa1.x, pa0.y, pa1.y};
#pragma unroll
                for (int nt = 0; nt < 16; ++nt) {
                    uint2 b = *(const uint2*)&sV[(nt * 8 + gg) * 72 + ks * 8 + 2 * t];
                    mma_tf32_u2(oacc[nt], a, b);
                }
            }
        }
    }

    // ---- normalize + write ----
    const float inv0 = 1.0f / lrow0, inv1 = 1.0f / lrow1;
    const int r0 = qrow0 + m0 + gg;
#pragma unroll
    for (int nt = 0; nt < 16; ++nt) {
        int cc = h * HD + nt * 8 + 2 * t;
        *(float2*)(o + (size_t)r0 * QD + cc) =
            make_float2(oacc[nt][0] * inv0, oacc[nt][1] * inv0);
        *(float2*)(o + (size_t)(r0 + 8) * QD + cc) =
            make_float2(oacc[nt][2] * inv1, oacc[nt][3] * inv1);
    }
}

// ---------------------------------------------------------------------------
extern "C" void kernel_launch(void* const* d_in, const int* in_sizes, int n_in,
                              void* d_out, int out_size)
{
    (void)in_sizes; (void)n_in; (void)out_size;
    const float* x   = (const float*)d_in[0];
    const float* mu  = (const float*)d_in[1];
    const float* wq  = (const float*)d_in[2];
    const float* wk  = (const float*)d_in[3];
    const float* wv  = (const float*)d_in[4];
    const float* wo  = (const float*)d_in[5];
    const float* wmq = (const float*)d_in[6];
    const float* wmk = (const float*)d_in[7];
    const float* wmv = (const float*)d_in[8];
    const float* qw  = (const float*)d_in[9];
    const float* kw  = (const float*)d_in[10];
    float* out = (float*)d_out;

    float *pq, *pk, *pv, *po;
    cudaGetSymbolAddress((void**)&pq, g_q);
    cudaGetSymbolAddress((void**)&pk, g_k);
    cudaGetSymbolAddress((void**)&pv, g_v);
    cudaGetSymbolAddress((void**)&po, g_o);

    const int gemm_smem = 4 * BUF_WORDS * 4;  // 73728 bytes
    cudaFuncSetAttribute(qkv_mma,   cudaFuncAttributeMaxDynamicSharedMemorySize, gemm_smem);
    cudaFuncSetAttribute(oproj_mma, cudaFuncAttributeMaxDynamicSharedMemorySize, gemm_smem);

    // Fused QKV projections on tensor cores (tf32), mu term folded as second K range
    qkv_mma<<<dim3(24, 16), 256, gemm_smem>>>(x, mu, wq, wmq, wk, wmk, wv, wmv, pq, pk, pv);

    // per-head RMSNorm + RoPE on q and k
    normrope_kernel<<<dim3(SEQ, NH + NKV), 128>>>(pq, pk, qw, kw);

    // causal GQA attention on tensor cores (tf32)
    const int attn_smem = ATTN_SMEM_WORDS * 4;  // 108544 bytes
    cudaFuncSetAttribute(attn_mma, cudaFuncAttributeMaxDynamicSharedMemorySize, attn_smem);
    attn_mma<<<dim3(SEQ / 128, NH), 256, attn_smem>>>(pq, pk, pv, po);

    // output projection on tensor cores (tf32)
    oproj_mma<<<dim3(16, 16), 256, gemm_smem>>>(po, wo, out);
}

// round 6
// speedup vs baseline: 3.8365x; 1.0180x over previous
#include <cuda_runtime.h>
#include <math.h>
#include <stdint.h>

#define SEQ 2048
#define HID 2048
#define NH 16
#define NKV 4
#define HD 128
#define QD (NH*HD)    /* 2048 */
#define KVD (NKV*HD)  /* 512  */

// Scratch (device globals: no allocations allowed)
__device__ float    g_q[SEQ*QD];
__device__ float    g_k[SEQ*KVD];
__device__ float    g_v[SEQ*KVD];
__device__ uint32_t g_o[SEQ*QD];             // attention output as tf32 bits
// Pre-converted tf32-bit operands (prepass)
__device__ uint32_t g_xmu[SEQ*2*HID];        // [x | mu]  2048 x 4096
__device__ uint32_t g_wqc[QD*2*HID];         // [wq | wmq] 2048 x 4096
__device__ uint32_t g_wkc[KVD*2*HID];        // [wk | wmk]  512 x 4096
__device__ uint32_t g_wvc[KVD*2*HID];        // [wv | wmv]  512 x 4096
__device__ uint32_t g_wot[HID*QD];           // wo         2048 x 2048

// ---------------------------------------------------------------------------
// tf32 helpers (plain sm_80+ PTX — no sm_103a-gated instructions)
// ---------------------------------------------------------------------------
__device__ __forceinline__ uint32_t f2tf32(float x) {
    uint32_t r;
    asm("cvt.rna.tf32.f32 %0, %1;" : "=r"(r) : "f"(x));
    return r;
}

__device__ __forceinline__ void mma_tf32(float d[4], const uint32_t a[4], const uint32_t b[2]) {
    asm volatile(
        "mma.sync.aligned.m16n8k8.row.col.f32.tf32.tf32.f32 "
        "{%0,%1,%2,%3}, {%4,%5,%6,%7}, {%8,%9}, {%0,%1,%2,%3};"
        : "+f"(d[0]), "+f"(d[1]), "+f"(d[2]), "+f"(d[3])
        : "r"(a[0]), "r"(a[1]), "r"(a[2]), "r"(a[3]), "r"(b[0]), "r"(b[1]));
}

__device__ __forceinline__ void mma_tf32_u2(float d[4], const uint32_t a[4], uint2 b) {
    asm volatile(
        "mma.sync.aligned.m16n8k8.row.col.f32.tf32.tf32.f32 "
        "{%0,%1,%2,%3}, {%4,%5,%6,%7}, {%8,%9}, {%0,%1,%2,%3};"
        : "+f"(d[0]), "+f"(d[1]), "+f"(d[2]), "+f"(d[3])
        : "r"(a[0]), "r"(a[1]), "r"(a[2]), "r"(a[3]), "r"(b.x), "r"(b.y));
}

#define CP_ASYNC_CG(dst_u32, src_ptr) \
    asm volatile("cp.async.cg.shared.global [%0], [%1], 16;" :: "r"(dst_u32), "l"(src_ptr) : "memory")
#define CP_COMMIT() asm volatile("cp.async.commit_group;" ::: "memory")
#define CP_WAIT1()  asm volatile("cp.async.wait_group 1;"  ::: "memory")

__device__ __forceinline__ uint32_t smem_u32(const void* p) {
    uint32_t a;
    asm("{ .reg .u64 t; cvta.to.shared.u64 t, %1; cvt.u32.u64 %0, t; }" : "=r"(a) : "l"(p));
    return a;
}

// ---------------------------------------------------------------------------
// Prepass conversion kernels (fp32 -> tf32 bits), float4-vectorized
// ---------------------------------------------------------------------------
__global__ __launch_bounds__(256) void cvt_cat(
    uint32_t* __restrict__ dst, const float* __restrict__ A,
    const float* __restrict__ B, int K, int K2)
{
    long e = ((long)blockIdx.x * 256 + threadIdx.x) * 4;
    int r = (int)(e / K2);
    int c = (int)(e % K2);
    const float* src = (c < K) ? (A + (size_t)r * K + c) : (B + (size_t)r * K + (c - K));
    float4 v = *(const float4*)src;
    uint4 u = make_uint4(f2tf32(v.x), f2tf32(v.y), f2tf32(v.z), f2tf32(v.w));
    *(uint4*)(dst + e) = u;
}

__global__ __launch_bounds__(256) void cvt_plain(
    uint32_t* __restrict__ dst, const float* __restrict__ src)
{
    long e = ((long)blockIdx.x * 256 + threadIdx.x) * 4;
    float4 v = *(const float4*)(src + e);
    *(uint4*)(dst + e) = make_uint4(f2tf32(v.x), f2tf32(v.y), f2tf32(v.z), f2tf32(v.w));
}

// ---------------------------------------------------------------------------
// cp.async 3-stage tf32 GEMM core: C[128,128] = A[128,K] @ B[128,K]^T.
// Operands are pre-converted tf32 bit arrays. 256 threads, BK=32 words.
// SMEM stage = A[128][36] + B[128][36] words (36KB); 3 stages = 108KB.
// Mainloop: wait(1) -> sync -> issue c+2 -> commit -> mma(c). The sync at
// iter c guarantees all warps finished mma(c-1), so reusing buffer
// (c+2)%3 == (c-1)%3 is hazard-free.
// ---------------------------------------------------------------------------
#define STG_WORDS 4608            /* 128*36 */
#define STAGE_WORDS (2*STG_WORDS) /* A+B */

__device__ __forceinline__ void gemm_core_async(
    const uint32_t* __restrict__ Ablk, const uint32_t* __restrict__ Bblk,
    float* __restrict__ Cblk, int ldc, int K, uint32_t* s)
{
    const uint32_t sbyte = smem_u32(s);
    const int tid = threadIdx.x;
    const int wid = tid >> 5, lane = tid & 31;
    const int g = lane >> 2, t = lane & 3;
    const int m0 = (wid >> 2) * 64;
    const int n0 = (wid & 3) * 32;

    const int lr = tid >> 3;          // 0..31
    const int lc4 = (tid & 7) * 4;    // word offset of 16B chunk

    float acc[4][4][4];
#pragma unroll
    for (int i = 0; i < 4; ++i)
#pragma unroll
        for (int j = 0; j < 4; ++j)
#pragma unroll
            for (int q = 0; q < 4; ++q) acc[i][j][q] = 0.0f;

    const int nch = K >> 5;

    // issue loads for chunk cc into stage st
    auto issue = [&](int st, int cc) {
        const uint32_t sa0 = sbyte + (uint32_t)(st * STAGE_WORDS) * 4u;
        const uint32_t sb0 = sa0 + STG_WORDS * 4u;
        const int kk = cc << 5;
#pragma unroll
        for (int i = 0; i < 4; ++i) {
            int r = lr + i * 32;
            uint32_t so = (uint32_t)(r * 36 + lc4) * 4u;
            CP_ASYNC_CG(sa0 + so, Ablk + (size_t)r * K + kk + lc4);
            CP_ASYNC_CG(sb0 + so, Bblk + (size_t)r * K + kk + lc4);
        }
    };

    issue(0, 0); CP_COMMIT();
    issue(1, 1); CP_COMMIT();

    for (int c = 0; c < nch; ++c) {
        CP_WAIT1();
        __syncthreads();
        if (c + 2 < nch) issue((c + 2) % 3, c + 2);
        CP_COMMIT();

        const uint32_t* sA = s + (c % 3) * STAGE_WORDS;
        const uint32_t* sB = sA + STG_WORDS;
#pragma unroll
        for (int ks = 0; ks < 4; ++ks) {
            uint32_t af[4][4], bf[4][2];
#pragma unroll
            for (int mt = 0; mt < 4; ++mt) {
                int mr = m0 + mt * 16 + g;
                af[mt][0] = sA[mr * 36 + ks * 8 + t];
                af[mt][1] = sA[(mr + 8) * 36 + ks * 8 + t];
                af[mt][2] = sA[mr * 36 + ks * 8 + t + 4];
                af[mt][3] = sA[(mr + 8) * 36 + ks * 8 + t + 4];
            }
#pragma unroll
            for (int nt = 0; nt < 4; ++nt) {
                int nr = n0 + nt * 8 + g;
                bf[nt][0] = sB[nr * 36 + ks * 8 + t];
                bf[nt][1] = sB[nr * 36 + ks * 8 + t + 4];
            }
#pragma unroll
            for (int mt = 0; mt < 4; ++mt)
#pragma unroll
                for (int nt = 0; nt < 4; ++nt)
                    mma_tf32(acc[mt][nt], af[mt], bf[nt]);
        }
    }

#pragma unroll
    for (int mt = 0; mt < 4; ++mt) {
        int r0 = m0 + mt * 16 + g;
#pragma unroll
        for (int nt = 0; nt < 4; ++nt) {
            int cc = n0 + nt * 8 + 2 * t;
            *(float2*)(Cblk + (size_t)r0 * ldc + cc)       = make_float2(acc[mt][nt][0], acc[mt][nt][1]);
            *(float2*)(Cblk + (size_t)(r0 + 8) * ldc + cc) = make_float2(acc[mt][nt][2], acc[mt][nt][3]);
        }
    }
}

// Fused QKV projection: grid = (24, 16). Col blocks 0..15 -> Q, 16..19 -> K, 20..23 -> V.
__global__ __launch_bounds__(256, 2) void qkv_mma(
    const uint32_t* __restrict__ xmu,
    const uint32_t* __restrict__ wqc, const uint32_t* __restrict__ wkc,
    const uint32_t* __restrict__ wvc,
    float* __restrict__ pq, float* __restrict__ pk, float* __restrict__ pv)
{
    extern __shared__ uint32_t smem[];
    const int cb = blockIdx.x;
    const int row0 = blockIdx.y * 128;

    const uint32_t* B; float* C; int ldc, ccol;
    if (cb < 16)      { B = wqc; C = pq; ldc = QD;  ccol = cb * 128; }
    else if (cb < 20) { B = wkc; C = pk; ldc = KVD; ccol = (cb - 16) * 128; }
    else              { B = wvc; C = pv; ldc = KVD; ccol = (cb - 20) * 128; }

    gemm_core_async(xmu + (size_t)row0 * (2 * HID), B + (size_t)ccol * (2 * HID),
                    C + (size_t)row0 * ldc + ccol, ldc, 2 * HID, smem);
}

// Output projection: grid = (16, 16)
__global__ __launch_bounds__(256, 2) void oproj_mma(
    const uint32_t* __restrict__ A, const uint32_t* __restrict__ B, float* __restrict__ C)
{
    extern __shared__ uint32_t smem[];
    const int row0 = blockIdx.y * 128;
    const int ccol = blockIdx.x * 128;
    gemm_core_async(A + (size_t)row0 * QD, B + (size_t)ccol * QD,
                    C + (size_t)row0 * QD + ccol, QD, QD, smem);
}

// ---------------------------------------------------------------------------
// Per-head RMSNorm + RoPE (in place on g_q / g_k). grid=(SEQ, NH+NKV), 128 thr
// ---------------------------------------------------------------------------
__global__ __launch_bounds__(128) void normrope_kernel(
    float* __restrict__ qb, float* __restrict__ kb,
    const float* __restrict__ qw, const float* __restrict__ kw)
{
    const int pos = blockIdx.x;
    const int hh = blockIdx.y;
    const int d = threadIdx.x;

    float* buf; int stride, col0; const float* w;
    if (hh < NH) { buf = qb; stride = QD;  col0 = hh * HD;        w = qw; }
    else         { buf = kb; stride = KVD; col0 = (hh - NH) * HD; w = kw; }

    const size_t idx = (size_t)pos * stride + col0 + d;
    float x = buf[idx];

    float ss = x * x;
#pragma unroll
    for (int off = 16; off; off >>= 1) ss += __shfl_xor_sync(0xffffffffu, ss, off);

    __shared__ float red[4];
    __shared__ float xs[128];
    if ((d & 31) == 0) red[d >> 5] = ss;
    __syncthreads();
    ss = red[0] + red[1] + red[2] + red[3];

    float xn = x * rsqrtf(ss * (1.0f / 128.0f) + 1e-6f) * w[d];
    xs[d] = xn;
    __syncthreads();
    float rot = (d < 64) ? -xs[d + 64] : xs[d - 64];

    float fi = (float)(d & 63);
    float ang = (float)pos * powf(10000.0f, -fi * (1.0f / 64.0f));
    float sn, cs;
    sincosf(ang, &sn, &cs);
    buf[idx] = xn * cs + rot * sn;
}

// ---------------------------------------------------------------------------
// Tensor-core causal flash attention (tf32 mma).
// Q-tile 128 rows, KV-tile 64. 8 warps (256 thr). grid = (SEQ/128, NH).
// Writes O as tf32 bits into g_o (consumed raw by oproj).
// ---------------------------------------------------------------------------
#define ATTN_SMEM_WORDS 27136

__global__ __launch_bounds__(256, 1) void attn_mma(
    const float* __restrict__ q, const float* __restrict__ k,
    const float* __restrict__ v, uint32_t* __restrict__ o)
{
    extern __shared__ uint32_t sw[];
    uint32_t* sK = sw;            // [64][136]
    uint32_t* sV = sw + 8704;     // [128][72]
    uint32_t* sP = sw + 17920;    // [128][72]
    uint32_t* sQ = sw;            // staging [128][136] (overlaps K+V)

    const int qt = gridDim.x - 1 - blockIdx.x;   // heavy tiles first
    const int h = blockIdx.y;
    const int kvh = h >> 2;
    const int qrow0 = qt * 128;
    const int tid = threadIdx.x;
    const int w = tid >> 5, lane = tid & 31;
    const int gg = lane >> 2, t = lane & 3;
    const int m0 = w * 16;

    // ---- stage Q tile into permuted smem (coalesced) ----
#pragma unroll
    for (int i = 0; i < 16; ++i) {
        int id = tid + i * 256;
        int r = id >> 5, c4 = id & 31, c = c4 * 4;
        float4 val = *(const float4*)(q + (size_t)(qrow0 + r) * QD + h * HD + c);
        uint32_t base = (uint32_t)(r * 136 + (c >> 3) * 8 + ((c >> 2) & 1));
        sQ[base + 0] = f2tf32(val.x);
        sQ[base + 2] = f2tf32(val.y);
        sQ[base + 4] = f2tf32(val.z);
        sQ[base + 6] = f2tf32(val.w);
    }
    __syncthreads();

    // ---- load Q fragments into registers ----
    uint32_t qf[16][4];
#pragma unroll
    for (int ks = 0; ks < 16; ++ks) {
        uint2 q0 = *(const uint2*)&sQ[(m0 + gg) * 136 + ks * 8 + 2 * t];
        uint2 q1 = *(const uint2*)&sQ[(m0 + gg + 8) * 136 + ks * 8 + 2 * t];
        qf[ks][0] = q0.x; qf[ks][1] = q1.x; qf[ks][2] = q0.y; qf[ks][3] = q1.y;
    }
    __syncthreads();

    float oacc[16][4];
#pragma unroll
    for (int i = 0; i < 16; ++i)
#pragma unroll
        for (int j = 0; j < 4; ++j) oacc[i][j] = 0.0f;
    float mrow0 = -1e30f, mrow1 = -1e30f, lrow0 = 0.0f, lrow1 = 0.0f;

    const float scale = 0.08838834764831845f;  // 1/sqrt(128)
    const int jmax = 2 * qt + 2;

    for (int jt = 0; jt < jmax; ++jt) {
        if (jt) __syncthreads();

        // ---- load K tile ----
#pragma unroll
        for (int i = 0; i < 8; ++i) {
            int id = tid + i * 256;
            int r = id >> 5, c4 = id & 31, c = c4 * 4;
            float4 kv = *(const float4*)(k + (size_t)(jt * 64 + r) * KVD + kvh * HD + c);
            uint32_t kb = (uint32_t)(r * 136 + (c >> 3) * 8 + ((c >> 2) & 1));
            sK[kb + 0] = f2tf32(kv.x);
            sK[kb + 2] = f2tf32(kv.y);
            sK[kb + 4] = f2tf32(kv.z);
            sK[kb + 6] = f2tf32(kv.w);
        }
        // ---- load V tile transposed ----
#pragma unroll
        for (int i = 0; i < 8; ++i) {
            int id = tid + i * 256;
            int r = id & 63, c4 = id >> 6, c = c4 * 4;
            float4 vv = *(const float4*)(v + (size_t)(jt * 64 + r) * KVD + kvh * HD + c);
            uint32_t rp = (uint32_t)((r >> 3) * 8 + (r & 3) * 2 + ((r >> 2) & 1));
            sV[(c + 0) * 72 + rp] = f2tf32(vv.x);
            sV[(c + 1) * 72 + rp] = f2tf32(vv.y);
            sV[(c + 2) * 72 + rp] = f2tf32(vv.z);
            sV[(c + 3) * 72 + rp] = f2tf32(vv.w);
        }
        __syncthreads();

        const bool active = (jt * 64 <= qrow0 + m0 + 15);
        if (active) {
            // ---- S = Q @ K^T ----
            float sacc[8][4];
#pragma unroll
            for (int i = 0; i < 8; ++i)
#pragma unroll
                for (int j = 0; j < 4; ++j) sacc[i][j] = 0.0f;

#pragma unroll
            for (int ks = 0; ks < 16; ++ks) {
#pragma unroll
                for (int nt = 0; nt < 8; ++nt) {
                    uint2 b = *(const uint2*)&sK[(nt * 8 + gg) * 136 + ks * 8 + 2 * t];
                    mma_tf32_u2(sacc[nt], qf[ks], b);
                }
            }

            // ---- scale + mask + online softmax ----
            const int r0 = qrow0 + m0 + gg;
            const int r1 = r0 + 8;
            const bool edge = (jt >= 2 * qt);
            float rm0 = -1e30f, rm1 = -1e30f;
#pragma unroll
            for (int nt = 0; nt < 8; ++nt) {
                float c0 = sacc[nt][0] * scale, c1 = sacc[nt][1] * scale;
                float c2 = sacc[nt][2] * scale, c3 = sacc[nt][3] * scale;
                if (edge) {
                    int colb = jt * 64 + nt * 8 + 2 * t;
                    if (colb     > r0) c0 = -1e30f;
                    if (colb + 1 > r0) c1 = -1e30f;
                    if (colb     > r1) c2 = -1e30f;
                    if (colb + 1 > r1) c3 = -1e30f;
                }
                sacc[nt][0] = c0; sacc[nt][1] = c1; sacc[nt][2] = c2; sacc[nt][3] = c3;
                rm0 = fmaxf(rm0, fmaxf(c0, c1));
                rm1 = fmaxf(rm1, fmaxf(c2, c3));
            }
            rm0 = fmaxf(rm0, __shfl_xor_sync(0xffffffffu, rm0, 1));
            rm0 = fmaxf(rm0, __shfl_xor_sync(0xffffffffu, rm0, 2));
            rm1 = fmaxf(rm1, __shfl_xor_sync(0xffffffffu, rm1, 1));
            rm1 = fmaxf(rm1, __shfl_xor_sync(0xffffffffu, rm1, 2));

            float mn0 = fmaxf(mrow0, rm0), mn1 = fmaxf(mrow1, rm1);
            float al0 = __expf(mrow0 - mn0), al1 = __expf(mrow1 - mn1);
            mrow0 = mn0; mrow1 = mn1;

            const uint32_t pA = (uint32_t)(((2 * t) & 3) * 2 + ((t >> 1) & 1));
            const uint32_t pb0 = (uint32_t)((m0 + gg) * 72) + pA;
            const uint32_t pb1 = pb0 + 8 * 72;
            float rs0 = 0.0f, rs1 = 0.0f;
#pragma unroll
            for (int nt = 0; nt < 8; ++nt) {
                float p0 = __expf(sacc[nt][0] - mn0);
                float p1 = __expf(sacc[nt][1] - mn0);
                float p2 = __expf(sacc[nt][2] - mn1);
                float p3 = __expf(sacc[nt][3] - mn1);
                rs0 += p0 + p1; rs1 += p2 + p3;
                sP[pb0 + nt * 8]     = f2tf32(p0);
                sP[pb0 + nt * 8 + 2] = f2tf32(p1);
                sP[pb1 + nt * 8]     = f2tf32(p2);
                sP[pb1 + nt * 8 + 2] = f2tf32(p3);
            }
            rs0 += __shfl_xor_sync(0xffffffffu, rs0, 1);
            rs0 += __shfl_xor_sync(0xffffffffu, rs0, 2);
            rs1 += __shfl_xor_sync(0xffffffffu, rs1, 1);
            rs1 += __shfl_xor_sync(0xffffffffu, rs1, 2);
            lrow0 = lrow0 * al0 + rs0;
            lrow1 = lrow1 * al1 + rs1;

#pragma unroll
            for (int nt = 0; nt < 16; ++nt) {
                oacc[nt][0] *= al0; oacc[nt][1] *= al0;
                oacc[nt][2] *= al1; oacc[nt][3] *= al1;
            }
            __syncwarp();

            // ---- O += P @ V ----
#pragma unroll
            for (int ks = 0; ks < 8; ++ks) {
                uint2 pa0 = *(const uint2*)&sP[(m0 + gg) * 72 + ks * 8 + 2 * t];
                uint2 pa1 = *(const uint2*)&sP[(m0 + gg + 8) * 72 + ks * 8 + 2 * t];
                uint32_t a[4] = {pa0.x, pa1.x, pa0.y, pa1.y};
#pragma unroll
                for (int nt = 0; nt < 16; ++nt) {
                    uint2 b = *(const uint2*)&sV[(nt * 8 + gg) * 72 + ks * 8 + 2 * t];
                    mma_tf32_u2(oacc[nt], a, b);
                }
            }
        }
    }

    // ---- normalize + write tf32 bits ----
    const float inv0 = 1.0f / lrow0, inv1 = 1.0f / lrow1;
    const int r0 = qrow0 + m0 + gg;
#pragma unroll
    for (int nt = 0; nt < 16; ++nt) {
        int cc = h * HD + nt * 8 + 2 * t;
        *(uint2*)(o + (size_t)r0 * QD + cc) =
            make_uint2(f2tf32(oacc[nt][0] * inv0), f2tf32(oacc[nt][1] * inv0));
        *(uint2*)(o + (size_t)(r0 + 8) * QD + cc) =
            make_uint2(f2tf32(oacc[nt][2] * inv1), f2tf32(oacc[nt][3] * inv1));
    }
}

// ---------------------------------------------------------------------------
extern "C" void kernel_launch(void* const* d_in, const int* in_sizes, int n_in,
                              void* d_out, int out_size)
{
    (void)in_sizes; (void)n_in; (void)out_size;
    const float* x   = (const float*)d_in[0];
    const float* mu  = (const float*)d_in[1];
    const float* wq  = (const float*)d_in[2];
    const float* wk  = (const float*)d_in[3];
    const float* wv  = (const float*)d_in[4];
    const float* wo  = (const float*)d_in[5];
    const float* wmq = (const float*)d_in[6];
    const float* wmk = (const float*)d_in[7];
    const float* wmv = (const float*)d_in[8];
    const float* qw  = (const float*)d_in[9];
    const float* kw  = (const float*)d_in[10];
    float* out = (float*)d_out;

    float *pq, *pk, *pv; uint32_t *po;
    uint32_t *pxmu, *pwqc, *pwkc, *pwvc, *pwot;
    cudaGetSymbolAddress((void**)&pq, g_q);
    cudaGetSymbolAddress((void**)&pk, g_k);
    cudaGetSymbolAddress((void**)&pv, g_v);
    cudaGetSymbolAddress((void**)&po, g_o);
    cudaGetSymbolAddress((void**)&pxmu, g_xmu);
    cudaGetSymbolAddress((void**)&pwqc, g_wqc);
    cudaGetSymbolAddress((void**)&pwkc, g_wkc);
    cudaGetSymbolAddress((void**)&pwvc, g_wvc);
    cudaGetSymbolAddress((void**)&pwot, g_wot);

    // ---- prepass: convert + concat to tf32 bits ----
    cvt_cat<<<(SEQ * 2 * HID) / 1024, 256>>>(pxmu, x, mu, HID, 2 * HID);
    cvt_cat<<<(QD * 2 * HID) / 1024, 256>>>(pwqc, wq, wmq, HID, 2 * HID);
    cvt_cat<<<(KVD * 2 * HID) / 1024, 256>>>(pwkc, wk, wmk, HID, 2 * HID);
    cvt_cat<<<(KVD * 2 * HID) / 1024, 256>>>(pwvc, wv, wmv, HID, 2 * HID);
    cvt_plain<<<(HID * QD) / 1024, 256>>>(pwot, wo);

    const int gemm_smem = 3 * STAGE_WORDS * 4;  // 110592 bytes
    cudaFuncSetAttribute(qkv_mma,   cudaFuncAttributeMaxDynamicSharedMemorySize, gemm_smem);
    cudaFuncSetAttribute(oproj_mma, cudaFuncAttributeMaxDynamicSharedMemorySize, gemm_smem);

    // Fused QKV projections (tf32, cp.async pipelined)
    qkv_mma<<<dim3(24, 16), 256, gemm_smem>>>(pxmu, pwqc, pwkc, pwvc, pq, pk, pv);

    // per-head RMSNorm + RoPE on q and k
    normrope_kernel<<<dim3(SEQ, NH + NKV), 128>>>(pq, pk, qw, kw);

    // causal GQA attention on tensor cores (tf32)
    const int attn_smem = ATTN_SMEM_WORDS * 4;  // 108544 bytes
    cudaFuncSetAttribute(attn_mma, cudaFuncAttributeMaxDynamicSharedMemorySize, attn_smem);
    attn_mma<<<dim3(SEQ / 128, NH), 256, attn_smem>>>(pq, pk, pv, po);

    // output projection (tf32, cp.async pipelined)
    oproj_mma<<<dim3(16, 16), 256, gemm_smem>>>(po, pwot, out);
}

// round 7
// speedup vs baseline: 4.2754x; 1.1144x over previous
#include <cuda_runtime.h>
#include <math.h>
#include <stdint.h>

#define SEQ 2048
#define HID 2048
#define NH 16
#define NKV 4
#define HD 128
#define QD (NH*HD)    /* 2048 */
#define KVD (NKV*HD)  /* 512  */

// Scratch (device globals: no allocations allowed)
__device__ float    g_q[SEQ*QD];
__device__ float    g_k[SEQ*KVD];
__device__ float    g_v[SEQ*KVD];
__device__ uint32_t g_o[SEQ*QD];             // attention output as tf32 bits
// Pre-converted tf32-bit operands (prepass)
__device__ uint32_t g_xmu[SEQ*2*HID];        // [x | mu]  2048 x 4096
__device__ uint32_t g_wqc[QD*2*HID];         // [wq | wmq] 2048 x 4096
__device__ uint32_t g_wkc[KVD*2*HID];        // [wk | wmk]  512 x 4096
__device__ uint32_t g_wvc[KVD*2*HID];        // [wv | wmv]  512 x 4096
__device__ uint32_t g_wot[HID*QD];           // wo         2048 x 2048

// ---------------------------------------------------------------------------
// tf32 helpers (plain sm_80+ PTX — no sm_103a-gated instructions)
// ---------------------------------------------------------------------------
__device__ __forceinline__ uint32_t f2tf32(float x) {
    uint32_t r;
    asm("cvt.rna.tf32.f32 %0, %1;" : "=r"(r) : "f"(x));
    return r;
}

__device__ __forceinline__ void mma_tf32(float d[4], const uint32_t a[4], const uint32_t b[2]) {
    asm volatile(
        "mma.sync.aligned.m16n8k8.row.col.f32.tf32.tf32.f32 "
        "{%0,%1,%2,%3}, {%4,%5,%6,%7}, {%8,%9}, {%0,%1,%2,%3};"
        : "+f"(d[0]), "+f"(d[1]), "+f"(d[2]), "+f"(d[3])
        : "r"(a[0]), "r"(a[1]), "r"(a[2]), "r"(a[3]), "r"(b[0]), "r"(b[1]));
}

__device__ __forceinline__ void mma_tf32_u2(float d[4], const uint32_t a[4], uint2 b) {
    asm volatile(
        "mma.sync.aligned.m16n8k8.row.col.f32.tf32.tf32.f32 "
        "{%0,%1,%2,%3}, {%4,%5,%6,%7}, {%8,%9}, {%0,%1,%2,%3};"
        : "+f"(d[0]), "+f"(d[1]), "+f"(d[2]), "+f"(d[3])
        : "r"(a[0]), "r"(a[1]), "r"(a[2]), "r"(a[3]), "r"(b.x), "r"(b.y));
}

#define CP_ASYNC_CG(dst_u32, src_ptr) \
    asm volatile("cp.async.cg.shared.global [%0], [%1], 16;" :: "r"(dst_u32), "l"(src_ptr) : "memory")
#define CP_COMMIT() asm volatile("cp.async.commit_group;" ::: "memory")
#define CP_WAIT1()  asm volatile("cp.async.wait_group 1;"  ::: "memory")

__device__ __forceinline__ uint32_t smem_u32(const void* p) {
    uint32_t a;
    asm("{ .reg .u64 t; cvta.to.shared.u64 t, %1; cvt.u32.u64 %0, t; }" : "=r"(a) : "l"(p));
    return a;
}

// ---------------------------------------------------------------------------
// Prepass conversion kernels (fp32 -> tf32 bits), float4-vectorized
// ---------------------------------------------------------------------------
__global__ __launch_bounds__(256) void cvt_cat(
    uint32_t* __restrict__ dst, const float* __restrict__ A,
    const float* __restrict__ B, int K, int K2)
{
    long e = ((long)blockIdx.x * 256 + threadIdx.x) * 4;
    int r = (int)(e / K2);
    int c = (int)(e % K2);
    const float* src = (c < K) ? (A + (size_t)r * K + c) : (B + (size_t)r * K + (c - K));
    float4 v = *(const float4*)src;
    uint4 u = make_uint4(f2tf32(v.x), f2tf32(v.y), f2tf32(v.z), f2tf32(v.w));
    *(uint4*)(dst + e) = u;
}

__global__ __launch_bounds__(256) void cvt_plain(
    uint32_t* __restrict__ dst, const float* __restrict__ src)
{
    long e = ((long)blockIdx.x * 256 + threadIdx.x) * 4;
    float4 v = *(const float4*)(src + e);
    *(uint4*)(dst + e) = make_uint4(f2tf32(v.x), f2tf32(v.y), f2tf32(v.z), f2tf32(v.w));
}

// ---------------------------------------------------------------------------
// cp.async 3-stage tf32 GEMM core: C[128,128] = A[128,K] @ B[128,K]^T.
// XOR-swizzled SMEM: 16B chunk c of row r stored at chunk (c ^ (r&7)).
// Rows are exactly 32 words -> stage = 2*16KB = 32KB, 3 stages = 96KB
// -> 2 CTAs/SM co-reside. Fragment loads are conflict-free under the swizzle.
// Mainloop: wait(1) -> sync -> issue c+2 -> commit -> mma(c).
// ---------------------------------------------------------------------------
#define STG_WORDS 4096            /* 128*32 */
#define STAGE_WORDS (2*STG_WORDS) /* A+B */

__device__ __forceinline__ void gemm_core_async(
    const uint32_t* __restrict__ Ablk, const uint32_t* __restrict__ Bblk,
    float* __restrict__ Cblk, int ldc, int K, uint32_t* s)
{
    const uint32_t sbyte = smem_u32(s);
    const int tid = threadIdx.x;
    const int wid = tid >> 5, lane = tid & 31;
    const int g = lane >> 2, t = lane & 3;
    const int m0 = (wid >> 2) * 64;
    const int n0 = (wid & 3) * 32;

    const int lr = tid >> 3;          // 0..31: base row
    const int ch = tid & 7;           // 16B chunk index 0..7

    float acc[4][4][4];
#pragma unroll
    for (int i = 0; i < 4; ++i)
#pragma unroll
        for (int j = 0; j < 4; ++j)
#pragma unroll
            for (int q = 0; q < 4; ++q) acc[i][j][q] = 0.0f;

    const int nch = K >> 5;
    const int chsw = ch ^ (lr & 7);   // swizzled chunk (row&7 invariant over i)

    auto issue = [&](int st, int cc) {
        const uint32_t sa0 = sbyte + (uint32_t)(st * STAGE_WORDS) * 4u;
        const uint32_t sb0 = sa0 + STG_WORDS * 4u;
        const int kk = cc << 5;
#pragma unroll
        for (int i = 0; i < 4; ++i) {
            int r = lr + i * 32;
            uint32_t so = (uint32_t)(r * 32 + chsw * 4) * 4u;
            CP_ASYNC_CG(sa0 + so, Ablk + (size_t)r * K + kk + ch * 4);
            CP_ASYNC_CG(sb0 + so, Bblk + (size_t)r * K + kk + ch * 4);
        }
    };

    issue(0, 0); CP_COMMIT();
    issue(1, 1); CP_COMMIT();

    for (int c = 0; c < nch; ++c) {
        CP_WAIT1();
        __syncthreads();
        if (c + 2 < nch) issue((c + 2) % 3, c + 2);
        CP_COMMIT();

        const uint32_t* sA = s + (c % 3) * STAGE_WORDS;
        const uint32_t* sB = sA + STG_WORDS;
#pragma unroll
        for (int ks = 0; ks < 4; ++ks) {
            const int e1 = (((2 * ks) ^ g) << 2) + t;        // swizzled word, chunk 2ks
            const int e2 = (((2 * ks) ^ g ^ 1) << 2) + t;    // swizzled word, chunk 2ks+1
            uint32_t af[4][4], bf[4][2];
#pragma unroll
            for (int mt = 0; mt < 4; ++mt) {
                int mr = m0 + mt * 16 + g;
                af[mt][0] = sA[mr * 32 + e1];
                af[mt][1] = sA[(mr + 8) * 32 + e1];
                af[mt][2] = sA[mr * 32 + e2];
                af[mt][3] = sA[(mr + 8) * 32 + e2];
            }
#pragma unroll
            for (int nt = 0; nt < 4; ++nt) {
                int nr = n0 + nt * 8 + g;
                bf[nt][0] = sB[nr * 32 + e1];
                bf[nt][1] = sB[nr * 32 + e2];
            }
#pragma unroll
            for (int mt = 0; mt < 4; ++mt)
#pragma unroll
                for (int nt = 0; nt < 4; ++nt)
                    mma_tf32(acc[mt][nt], af[mt], bf[nt]);
        }
    }

#pragma unroll
    for (int mt = 0; mt < 4; ++mt) {
        int r0 = m0 + mt * 16 + g;
#pragma unroll
        for (int nt = 0; nt < 4; ++nt) {
            int cc = n0 + nt * 8 + 2 * t;
            *(float2*)(Cblk + (size_t)r0 * ldc + cc)       = make_float2(acc[mt][nt][0], acc[mt][nt][1]);
            *(float2*)(Cblk + (size_t)(r0 + 8) * ldc + cc) = make_float2(acc[mt][nt][2], acc[mt][nt][3]);
        }
    }
}

// Fused QKV projection: grid = (24, 16). Col blocks 0..15 -> Q, 16..19 -> K, 20..23 -> V.
__global__ __launch_bounds__(256, 2) void qkv_mma(
    const uint32_t* __restrict__ xmu,
    const uint32_t* __restrict__ wqc, const uint32_t* __restrict__ wkc,
    const uint32_t* __restrict__ wvc,
    float* __restrict__ pq, float* __restrict__ pk, float* __restrict__ pv)
{
    extern __shared__ uint32_t smem[];
    const int cb = blockIdx.x;
    const int row0 = blockIdx.y * 128;

    const uint32_t* B; float* C; int ldc, ccol;
    if (cb < 16)      { B = wqc; C = pq; ldc = QD;  ccol = cb * 128; }
    else if (cb < 20) { B = wkc; C = pk; ldc = KVD; ccol = (cb - 16) * 128; }
    else              { B = wvc; C = pv; ldc = KVD; ccol = (cb - 20) * 128; }

    gemm_core_async(xmu + (size_t)row0 * (2 * HID), B + (size_t)ccol * (2 * HID),
                    C + (size_t)row0 * ldc + ccol, ldc, 2 * HID, smem);
}

// Output projection: grid = (16, 16)
__global__ __launch_bounds__(256, 2) void oproj_mma(
    const uint32_t* __restrict__ A, const uint32_t* __restrict__ B, float* __restrict__ C)
{
    extern __shared__ uint32_t smem[];
    const int row0 = blockIdx.y * 128;
    const int ccol = blockIdx.x * 128;
    gemm_core_async(A + (size_t)row0 * QD, B + (size_t)ccol * QD,
                    C + (size_t)row0 * QD + ccol, QD, QD, smem);
}

// ---------------------------------------------------------------------------
// Per-head RMSNorm + RoPE (in place on g_q / g_k). grid=(SEQ, NH+NKV), 128 thr
// ---------------------------------------------------------------------------
__global__ __launch_bounds__(128) void normrope_kernel(
    float* __restrict__ qb, float* __restrict__ kb,
    const float* __restrict__ qw, const float* __restrict__ kw)
{
    const int pos = blockIdx.x;
    const int hh = blockIdx.y;
    const int d = threadIdx.x;

    float* buf; int stride, col0; const float* w;
    if (hh < NH) { buf = qb; stride = QD;  col0 = hh * HD;        w = qw; }
    else         { buf = kb; stride = KVD; col0 = (hh - NH) * HD; w = kw; }

    const size_t idx = (size_t)pos * stride + col0 + d;
    float x = buf[idx];

    float ss = x * x;
#pragma unroll
    for (int off = 16; off; off >>= 1) ss += __shfl_xor_sync(0xffffffffu, ss, off);

    __shared__ float red[4];
    __shared__ float xs[128];
    if ((d & 31) == 0) red[d >> 5] = ss;
    __syncthreads();
    ss = red[0] + red[1] + red[2] + red[3];

    float xn = x * rsqrtf(ss * (1.0f / 128.0f) + 1e-6f) * w[d];
    xs[d] = xn;
    __syncthreads();
    float rot = (d < 64) ? -xs[d + 64] : xs[d - 64];

    float fi = (float)(d & 63);
    float ang = (float)pos * powf(10000.0f, -fi * (1.0f / 64.0f));
    float sn, cs;
    sincosf(ang, &sn, &cs);
    buf[idx] = xn * cs + rot * sn;
}

// ---------------------------------------------------------------------------
// Tensor-core causal flash attention (tf32 mma).
// Q-tile 128 rows, KV-tile 64. 8 warps (256 thr). grid = (SEQ/128, NH).
// Writes O as tf32 bits into g_o (consumed raw by oproj).
// ---------------------------------------------------------------------------
#define ATTN_SMEM_WORDS 27136

__global__ __launch_bounds__(256, 1) void attn_mma(
    const float* __restrict__ q, const float* __restrict__ k,
    const float* __restrict__ v, uint32_t* __restrict__ o)
{
    extern __shared__ uint32_t sw[];
    uint32_t* sK = sw;            // [64][136]
    uint32_t* sV = sw + 8704;     // [128][72]
    uint32_t* sP = sw + 17920;    // [128][72]
    uint32_t* sQ = sw;            // staging [128][136] (overlaps K+V)

    const int qt = gridDim.x - 1 - blockIdx.x;   // heavy tiles first
    const int h = blockIdx.y;
    const int kvh = h >> 2;
    const int qrow0 = qt * 128;
    const int tid = threadIdx.x;
    const int w = tid >> 5, lane = tid & 31;
    const int gg = lane >> 2, t = lane & 3;
    const int m0 = w * 16;

    // ---- stage Q tile into permuted smem (coalesced) ----
#pragma unroll
    for (int i = 0; i < 16; ++i) {
        int id = tid + i * 256;
        int r = id >> 5, c4 = id & 31, c = c4 * 4;
        float4 val = *(const float4*)(q + (size_t)(qrow0 + r) * QD + h * HD + c);
        uint32_t base = (uint32_t)(r * 136 + (c >> 3) * 8 + ((c >> 2) & 1));
        sQ[base + 0] = f2tf32(val.x);
        sQ[base + 2] = f2tf32(val.y);
        sQ[base + 4] = f2tf32(val.z);
        sQ[base + 6] = f2tf32(val.w);
    }
    __syncthreads();

    // ---- load Q fragments into registers ----
    uint32_t qf[16][4];
#pragma unroll
    for (int ks = 0; ks < 16; ++ks) {
        uint2 q0 = *(const uint2*)&sQ[(m0 + gg) * 136 + ks * 8 + 2 * t];
        uint2 q1 = *(const uint2*)&sQ[(m0 + gg + 8) * 136 + ks * 8 + 2 * t];
        qf[ks][0] = q0.x; qf[ks][1] = q1.x; qf[ks][2] = q0.y; qf[ks][3] = q1.y;
    }
    __syncthreads();

    float oacc[16][4];
#pragma unroll
    for (int i = 0; i < 16; ++i)
#pragma unroll
        for (int j = 0; j < 4; ++j) oacc[i][j] = 0.0f;
    float mrow0 = -1e30f, mrow1 = -1e30f, lrow0 = 0.0f, lrow1 = 0.0f;

    const float scale = 0.08838834764831845f;  // 1/sqrt(128)
    const int jmax = 2 * qt + 2;

    for (int jt = 0; jt < jmax; ++jt) {
        if (jt) __syncthreads();

        // ---- load K tile ----
#pragma unroll
        for (int i = 0; i < 8; ++i) {
            int id = tid + i * 256;
            int r = id >> 5, c4 = id & 31, c = c4 * 4;
            float4 kv = *(const float4*)(k + (size_t)(jt * 64 + r) * KVD + kvh * HD + c);
            uint32_t kb = (uint32_t)(r * 136 + (c >> 3) * 8 + ((c >> 2) & 1));
            sK[kb + 0] = f2tf32(kv.x);
            sK[kb + 2] = f2tf32(kv.y);
            sK[kb + 4] = f2tf32(kv.z);
            sK[kb + 6] = f2tf32(kv.w);
        }
        // ---- load V tile transposed ----
#pragma unroll
        for (int i = 0; i < 8; ++i) {
            int id = tid + i * 256;
            int r = id & 63, c4 = id >> 6, c = c4 * 4;
            float4 vv = *(const float4*)(v + (size_t)(jt * 64 + r) * KVD + kvh * HD + c);
            uint32_t rp = (uint32_t)((r >> 3) * 8 + (r & 3) * 2 + ((r >> 2) & 1));
            sV[(c + 0) * 72 + rp] = f2tf32(vv.x);
            sV[(c + 1) * 72 + rp] = f2tf32(vv.y);
            sV[(c + 2) * 72 + rp] = f2tf32(vv.z);
            sV[(c + 3) * 72 + rp] = f2tf32(vv.w);
        }
        __syncthreads();

        const bool active = (jt * 64 <= qrow0 + m0 + 15);
        if (active) {
            // ---- S = Q @ K^T ----
            float sacc[8][4];
#pragma unroll
            for (int i = 0; i < 8; ++i)
#pragma unroll
                for (int j = 0; j < 4; ++j) sacc[i][j] = 0.0f;

#pragma unroll
            for (int ks = 0; ks < 16; ++ks) {
#pragma unroll
                for (int nt = 0; nt < 8; ++nt) {
                    uint2 b = *(const uint2*)&sK[(nt * 8 + gg) * 136 + ks * 8 + 2 * t];
                    mma_tf32_u2(sacc[nt], qf[ks], b);
                }
            }

            // ---- scale + mask + online softmax ----
            const int r0 = qrow0 + m0 + gg;
            const int r1 = r0 + 8;
            const bool edge = (jt >= 2 * qt);
            float rm0 = -1e30f, rm1 = -1e30f;
#pragma unroll
            for (int nt = 0; nt < 8; ++nt) {
                float c0 = sacc[nt][0] * scale, c1 = sacc[nt][1] * scale;
                float c2 = sacc[nt][2] * scale, c3 = sacc[nt][3] * scale;
                if (edge) {
                    int colb = jt * 64 + nt * 8 + 2 * t;
                    if (colb     > r0) c0 = -1e30f;
                    if (colb + 1 > r0) c1 = -1e30f;
                    if (colb     > r1) c2 = -1e30f;
                    if (colb + 1 > r1) c3 = -1e30f;
                }
                sacc[nt][0] = c0; sacc[nt][1] = c1; sacc[nt][2] = c2; sacc[nt][3] = c3;
                rm0 = fmaxf(rm0, fmaxf(c0, c1));
                rm1 = fmaxf(rm1, fmaxf(c2, c3));
            }
            rm0 = fmaxf(rm0, __shfl_xor_sync(0xffffffffu, rm0, 1));
            rm0 = fmaxf(rm0, __shfl_xor_sync(0xffffffffu, rm0, 2));
            rm1 = fmaxf(rm1, __shfl_xor_sync(0xffffffffu, rm1, 1));
            rm1 = fmaxf(rm1, __shfl_xor_sync(0xffffffffu, rm1, 2));

            float mn0 = fmaxf(mrow0, rm0), mn1 = fmaxf(mrow1, rm1);
            float al0 = __expf(mrow0 - mn0), al1 = __expf(mrow1 - mn1);
            mrow0 = mn0; mrow1 = mn1;

            const uint32_t pA = (uint32_t)(((2 * t) & 3) * 2 + ((t >> 1) & 1));
            const uint32_t pb0 = (uint32_t)((m0 + gg) * 72) + pA;
            const uint32_t pb1 = pb0 + 8 * 72;
            float rs0 = 0.0f, rs1 = 0.0f;
#pragma unroll
            for (int nt = 0; nt < 8; ++nt) {
                float p0 = __expf(sacc[nt][0] - mn0);
                float p1 = __expf(sacc[nt][1] - mn0);
                float p2 = __expf(sacc[nt][2] - mn1);
                float p3 = __expf(sacc[nt][3] - mn1);
                rs0 += p0 + p1; rs1 += p2 + p3;
                sP[pb0 + nt * 8]     = f2tf32(p0);
                sP[pb0 + nt * 8 + 2] = f2tf32(p1);
                sP[pb1 + nt * 8]     = f2tf32(p2);
                sP[pb1 + nt * 8 + 2] = f2tf32(p3);
            }
            rs0 += __shfl_xor_sync(0xffffffffu, rs0, 1);
            rs0 += __shfl_xor_sync(0xffffffffu, rs0, 2);
            rs1 += __shfl_xor_sync(0xffffffffu, rs1, 1);
            rs1 += __shfl_xor_sync(0xffffffffu, rs1, 2);
            lrow0 = lrow0 * al0 + rs0;
            lrow1 = lrow1 * al1 + rs1;

#pragma unroll
            for (int nt = 0; nt < 16; ++nt) {
                oacc[nt][0] *= al0; oacc[nt][1] *= al0;
                oacc[nt][2] *= al1; oacc[nt][3] *= al1;
            }
            __syncwarp();

            // ---- O += P @ V ----
#pragma unroll
            for (int ks = 0; ks < 8; ++ks) {
                uint2 pa0 = *(const uint2*)&sP[(m0 + gg) * 72 + ks * 8 + 2 * t];
                uint2 pa1 = *(const uint2*)&sP[(m0 + gg + 8) * 72 + ks * 8 + 2 * t];
                uint32_t a[4] = {pa0.x, pa1.x, pa0.y, pa1.y};
#pragma unroll
                for (int nt = 0; nt < 16; ++nt) {
                    uint2 b = *(const uint2*)&sV[(nt * 8 + gg) * 72 + ks * 8 + 2 * t];
                    mma_tf32_u2(oacc[nt], a, b);
                }
            }
        }
    }

    // ---- normalize + write tf32 bits ----
    const float inv0 = 1.0f / lrow0, inv1 = 1.0f / lrow1;
    const int r0 = qrow0 + m0 + gg;
#pragma unroll
    for (int nt = 0; nt < 16; ++nt) {
        int cc = h * HD + nt * 8 + 2 * t;
        *(uint2*)(o + (size_t)r0 * QD + cc) =
            make_uint2(f2tf32(oacc[nt][0] * inv0), f2tf32(oacc[nt][1] * inv0));
        *(uint2*)(o + (size_t)(r0 + 8) * QD + cc) =
            make_uint2(f2tf32(oacc[nt][2] * inv1), f2tf32(oacc[nt][3] * inv1));
    }
}

// ---------------------------------------------------------------------------
extern "C" void kernel_launch(void* const* d_in, const int* in_sizes, int n_in,
                              void* d_out, int out_size)
{
    (void)in_sizes; (void)n_in; (void)out_size;
    const float* x   = (const float*)d_in[0];
    const float* mu  = (const float*)d_in[1];
    const float* wq  = (const float*)d_in[2];
    const float* wk  = (const float*)d_in[3];
    const float* wv  = (const float*)d_in[4];
    const float* wo  = (const float*)d_in[5];
    const float* wmq = (const float*)d_in[6];
    const float* wmk = (const float*)d_in[7];
    const float* wmv = (const float*)d_in[8];
    const float* qw  = (const float*)d_in[9];
    const float* kw  = (const float*)d_in[10];
    float* out = (float*)d_out;

    float *pq, *pk, *pv; uint32_t *po;
    uint32_t *pxmu, *pwqc, *pwkc, *pwvc, *pwot;
    cudaGetSymbolAddress((void**)&pq, g_q);
    cudaGetSymbolAddress((void**)&pk, g_k);
    cudaGetSymbolAddress((void**)&pv, g_v);
    cudaGetSymbolAddress((void**)&po, g_o);
    cudaGetSymbolAddress((void**)&pxmu, g_xmu);
    cudaGetSymbolAddress((void**)&pwqc, g_wqc);
    cudaGetSymbolAddress((void**)&pwkc, g_wkc);
    cudaGetSymbolAddress((void**)&pwvc, g_wvc);
    cudaGetSymbolAddress((void**)&pwot, g_wot);

    // ---- prepass: convert + concat to tf32 bits ----
    cvt_cat<<<(SEQ * 2 * HID) / 1024, 256>>>(pxmu, x, mu, HID, 2 * HID);
    cvt_cat<<<(QD * 2 * HID) / 1024, 256>>>(pwqc, wq, wmq, HID, 2 * HID);
    cvt_cat<<<(KVD * 2 * HID) / 1024, 256>>>(pwkc, wk, wmk, HID, 2 * HID);
    cvt_cat<<<(KVD * 2 * HID) / 1024, 256>>>(pwvc, wv, wmv, HID, 2 * HID);
    cvt_plain<<<(HID * QD) / 1024, 256>>>(pwot, wo);

    const int gemm_smem = 3 * STAGE_WORDS * 4;  // 98304 bytes
    cudaFuncSetAttribute(qkv_mma,   cudaFuncAttributeMaxDynamicSharedMemorySize, gemm_smem);
    cudaFuncSetAttribute(oproj_mma, cudaFuncAttributeMaxDynamicSharedMemorySize, gemm_smem);

    // Fused QKV projections (tf32, cp.async pipelined, 2 CTAs/SM)
    qkv_mma<<<dim3(24, 16), 256, gemm_smem>>>(pxmu, pwqc, pwkc, pwvc, pq, pk, pv);

    // per-head RMSNorm + RoPE on q and k
    normrope_kernel<<<dim3(SEQ, NH + NKV), 128>>>(pq, pk, qw, kw);

    // causal GQA attention on tensor cores (tf32)
    const int attn_smem = ATTN_SMEM_WORDS * 4;  // 108544 bytes
    cudaFuncSetAttribute(attn_mma, cudaFuncAttributeMaxDynamicSharedMemorySize, attn_smem);
    attn_mma<<<dim3(SEQ / 128, NH), 256, attn_smem>>>(pq, pk, pv, po);

    // output projection (tf32, cp.async pipelined, 2 CTAs/SM)
    oproj_mma<<<dim3(16, 16), 256, gemm_smem>>>(po, pwot, out);
}

// round 8
// speedup vs baseline: 4.7733x; 1.1165x over previous
#include <cuda_runtime.h>
#include <math.h>
#include <stdint.h>

#define SEQ 2048
#define HID 2048
#define NH 16
#define NKV 4
#define HD 128
#define QD (NH*HD)    /* 2048 */
#define KVD (NKV*HD)  /* 512  */

// Scratch (device globals: no allocations allowed)
__device__ float    g_q[SEQ*QD];
__device__ float    g_k[SEQ*KVD];            // fp32 K (pre-normrope)
__device__ uint32_t g_kt[SEQ*KVD];           // tf32 K (post-normrope)
__device__ uint32_t g_vt[KVD*SEQ];           // tf32 V, transposed [kvd][seq]
__device__ uint32_t g_o[SEQ*QD];             // attention output as tf32 bits
// Pre-converted tf32-bit operands (prepass)
__device__ uint32_t g_xmu[SEQ*2*HID];        // [x | mu]  2048 x 4096
__device__ uint32_t g_wqc[QD*2*HID];         // [wq | wmq] 2048 x 4096
__device__ uint32_t g_wkc[KVD*2*HID];        // [wk | wmk]  512 x 4096
__device__ uint32_t g_wvc[KVD*2*HID];        // [wv | wmv]  512 x 4096
__device__ uint32_t g_wot[HID*QD];           // wo         2048 x 2048

// ---------------------------------------------------------------------------
// tf32 helpers (plain sm_80+ PTX — no sm_103a-gated instructions)
// ---------------------------------------------------------------------------
__device__ __forceinline__ uint32_t f2tf32(float x) {
    uint32_t r;
    asm("cvt.rna.tf32.f32 %0, %1;" : "=r"(r) : "f"(x));
    return r;
}

__device__ __forceinline__ void mma_tf32(float d[4], const uint32_t a[4], const uint32_t b[2]) {
    asm volatile(
        "mma.sync.aligned.m16n8k8.row.col.f32.tf32.tf32.f32 "
        "{%0,%1,%2,%3}, {%4,%5,%6,%7}, {%8,%9}, {%0,%1,%2,%3};"
        : "+f"(d[0]), "+f"(d[1]), "+f"(d[2]), "+f"(d[3])
        : "r"(a[0]), "r"(a[1]), "r"(a[2]), "r"(a[3]), "r"(b[0]), "r"(b[1]));
}

__device__ __forceinline__ void mma_tf32_2(float d[4], const uint32_t a[4],
                                           uint32_t b0, uint32_t b1) {
    asm volatile(
        "mma.sync.aligned.m16n8k8.row.col.f32.tf32.tf32.f32 "
        "{%0,%1,%2,%3}, {%4,%5,%6,%7}, {%8,%9}, {%0,%1,%2,%3};"
        : "+f"(d[0]), "+f"(d[1]), "+f"(d[2]), "+f"(d[3])
        : "r"(a[0]), "r"(a[1]), "r"(a[2]), "r"(a[3]), "r"(b0), "r"(b1));
}

__device__ __forceinline__ void mma_tf32_u2(float d[4], const uint32_t a[4], uint2 b) {
    mma_tf32_2(d, a, b.x, b.y);
}

#define CP_ASYNC_CG(dst_u32, src_ptr) \
    asm volatile("cp.async.cg.shared.global [%0], [%1], 16;" :: "r"(dst_u32), "l"(src_ptr) : "memory")
#define CP_COMMIT() asm volatile("cp.async.commit_group;" ::: "memory")
#define CP_WAIT1()  asm volatile("cp.async.wait_group 1;"  ::: "memory")
#define CP_WAIT0()  asm volatile("cp.async.wait_group 0;"  ::: "memory")

__device__ __forceinline__ uint32_t smem_u32(const void* p) {
    uint32_t a;
    asm("{ .reg .u64 t; cvta.to.shared.u64 t, %1; cvt.u32.u64 %0, t; }" : "=r"(a) : "l"(p));
    return a;
}

// ---------------------------------------------------------------------------
// Prepass conversion kernels (fp32 -> tf32 bits), float4-vectorized
// ---------------------------------------------------------------------------
__global__ __launch_bounds__(256) void cvt_cat(
    uint32_t* __restrict__ dst, const float* __restrict__ A,
    const float* __restrict__ B, int K, int K2)
{
    long e = ((long)blockIdx.x * 256 + threadIdx.x) * 4;
    int r = (int)(e / K2);
    int c = (int)(e % K2);
    const float* src = (c < K) ? (A + (size_t)r * K + c) : (B + (size_t)r * K + (c - K));
    float4 v = *(const float4*)src;
    uint4 u = make_uint4(f2tf32(v.x), f2tf32(v.y), f2tf32(v.z), f2tf32(v.w));
    *(uint4*)(dst + e) = u;
}

__global__ __launch_bounds__(256) void cvt_plain(
    uint32_t* __restrict__ dst, const float* __restrict__ src)
{
    long e = ((long)blockIdx.x * 256 + threadIdx.x) * 4;
    float4 v = *(const float4*)(src + e);
    *(uint4*)(dst + e) = make_uint4(f2tf32(v.x), f2tf32(v.y), f2tf32(v.z), f2tf32(v.w));
}

// ---------------------------------------------------------------------------
// cp.async 3-stage tf32 GEMM core (XOR swizzle). TRANSV epilogue writes tf32
// bits transposed into Ct[(col0g+cc)*SEQ + row0g + r].
// ---------------------------------------------------------------------------
#define STG_WORDS 4096            /* 128*32 */
#define STAGE_WORDS (2*STG_WORDS) /* A+B */

template<bool TRANSV>
__device__ __forceinline__ void gemm_core_async(
    const uint32_t* __restrict__ Ablk, const uint32_t* __restrict__ Bblk,
    float* __restrict__ Cblk, int ldc,
    uint32_t* __restrict__ Ct, int row0g, int col0g,
    int K, uint32_t* s)
{
    const uint32_t sbyte = smem_u32(s);
    const int tid = threadIdx.x;
    const int wid = tid >> 5, lane = tid & 31;
    const int g = lane >> 2, t = lane & 3;
    const int m0 = (wid >> 2) * 64;
    const int n0 = (wid & 3) * 32;

    const int lr = tid >> 3;
    const int ch = tid & 7;

    float acc[4][4][4];
#pragma unroll
    for (int i = 0; i < 4; ++i)
#pragma unroll
        for (int j = 0; j < 4; ++j)
#pragma unroll
            for (int q = 0; q < 4; ++q) acc[i][j][q] = 0.0f;

    const int nch = K >> 5;
    const int chsw = ch ^ (lr & 7);

    auto issue = [&](int st, int cc) {
        const uint32_t sa0 = sbyte + (uint32_t)(st * STAGE_WORDS) * 4u;
        const uint32_t sb0 = sa0 + STG_WORDS * 4u;
        const int kk = cc << 5;
#pragma unroll
        for (int i = 0; i < 4; ++i) {
            int r = lr + i * 32;
            uint32_t so = (uint32_t)(r * 32 + chsw * 4) * 4u;
            CP_ASYNC_CG(sa0 + so, Ablk + (size_t)r * K + kk + ch * 4);
            CP_ASYNC_CG(sb0 + so, Bblk + (size_t)r * K + kk + ch * 4);
        }
    };

    issue(0, 0); CP_COMMIT();
    issue(1, 1); CP_COMMIT();

    for (int c = 0; c < nch; ++c) {
        CP_WAIT1();
        __syncthreads();
        if (c + 2 < nch) issue((c + 2) % 3, c + 2);
        CP_COMMIT();

        const uint32_t* sA = s + (c % 3) * STAGE_WORDS;
        const uint32_t* sB = sA + STG_WORDS;
#pragma unroll
        for (int ks = 0; ks < 4; ++ks) {
            const int e1 = (((2 * ks) ^ g) << 2) + t;
            const int e2 = (((2 * ks) ^ g ^ 1) << 2) + t;
            uint32_t af[4][4], bf[4][2];
#pragma unroll
            for (int mt = 0; mt < 4; ++mt) {
                int mr = m0 + mt * 16 + g;
                af[mt][0] = sA[mr * 32 + e1];
                af[mt][1] = sA[(mr + 8) * 32 + e1];
                af[mt][2] = sA[mr * 32 + e2];
                af[mt][3] = sA[(mr + 8) * 32 + e2];
            }
#pragma unroll
            for (int nt = 0; nt < 4; ++nt) {
                int nr = n0 + nt * 8 + g;
                bf[nt][0] = sB[nr * 32 + e1];
                bf[nt][1] = sB[nr * 32 + e2];
            }
#pragma unroll
            for (int mt = 0; mt < 4; ++mt)
#pragma unroll
                for (int nt = 0; nt < 4; ++nt)
                    mma_tf32(acc[mt][nt], af[mt], bf[nt]);
        }
    }

#pragma unroll
    for (int mt = 0; mt < 4; ++mt) {
        int r0 = m0 + mt * 16 + g;
#pragma unroll
        for (int nt = 0; nt < 4; ++nt) {
            int cc = n0 + nt * 8 + 2 * t;
            if (TRANSV) {
                Ct[(size_t)(col0g + cc)     * SEQ + row0g + r0]     = f2tf32(acc[mt][nt][0]);
                Ct[(size_t)(col0g + cc + 1) * SEQ + row0g + r0]     = f2tf32(acc[mt][nt][1]);
                Ct[(size_t)(col0g + cc)     * SEQ + row0g + r0 + 8] = f2tf32(acc[mt][nt][2]);
                Ct[(size_t)(col0g + cc + 1) * SEQ + row0g + r0 + 8] = f2tf32(acc[mt][nt][3]);
            } else {
                *(float2*)(Cblk + (size_t)r0 * ldc + cc)       = make_float2(acc[mt][nt][0], acc[mt][nt][1]);
                *(float2*)(Cblk + (size_t)(r0 + 8) * ldc + cc) = make_float2(acc[mt][nt][2], acc[mt][nt][3]);
            }
        }
    }
}

// Fused QKV: grid (24,16). cb 0..15 -> Q (fp32), 16..19 -> K (fp32),
// 20..23 -> V (tf32 bits, transposed into g_vt).
__global__ __launch_bounds__(256, 2) void qkv_mma(
    const uint32_t* __restrict__ xmu,
    const uint32_t* __restrict__ wqc, const uint32_t* __restrict__ wkc,
    const uint32_t* __restrict__ wvc,
    float* __restrict__ pq, float* __restrict__ pk, uint32_t* __restrict__ pvt)
{
    extern __shared__ uint32_t smem[];
    const int cb = blockIdx.x;
    const int row0 = blockIdx.y * 128;

    if (cb < 20) {
        const uint32_t* B; float* C; int ldc, ccol;
        if (cb < 16) { B = wqc; C = pq; ldc = QD;  ccol = cb * 128; }
        else         { B = wkc; C = pk; ldc = KVD; ccol = (cb - 16) * 128; }
        gemm_core_async<false>(xmu + (size_t)row0 * (2 * HID), B + (size_t)ccol * (2 * HID),
                               C + (size_t)row0 * ldc + ccol, ldc, nullptr, 0, 0, 2 * HID, smem);
    } else {
        const int ccol = (cb - 20) * 128;
        gemm_core_async<true>(xmu + (size_t)row0 * (2 * HID), wvc + (size_t)ccol * (2 * HID),
                              nullptr, 0, pvt, row0, ccol, 2 * HID, smem);
    }
}

// Output projection: grid = (16, 16)
__global__ __launch_bounds__(256, 2) void oproj_mma(
    const uint32_t* __restrict__ A, const uint32_t* __restrict__ B, float* __restrict__ C)
{
    extern __shared__ uint32_t smem[];
    const int row0 = blockIdx.y * 128;
    const int ccol = blockIdx.x * 128;
    gemm_core_async<false>(A + (size_t)row0 * QD, B + (size_t)ccol * QD,
                           C + (size_t)row0 * QD + ccol, QD, nullptr, 0, 0, QD, smem);
}

// ---------------------------------------------------------------------------
// Per-head RMSNorm + RoPE. Q in place (fp32); K: fp32 in -> tf32 bits out.
// grid=(SEQ, NH+NKV), 128 thr
// ---------------------------------------------------------------------------
__global__ __launch_bounds__(128) void normrope_kernel(
    float* __restrict__ qb, const float* __restrict__ kb, uint32_t* __restrict__ kt,
    const float* __restrict__ qw, const float* __restrict__ kw)
{
    const int pos = blockIdx.x;
    const int hh = blockIdx.y;
    const int d = threadIdx.x;

    const bool isq = (hh < NH);
    int stride = isq ? QD : KVD;
    int col0 = isq ? hh * HD : (hh - NH) * HD;
    const float* w = isq ? qw : kw;
    const size_t idx = (size_t)pos * stride + col0 + d;

    float x = isq ? qb[idx] : kb[idx];

    float ss = x * x;
#pragma unroll
    for (int off = 16; off; off >>= 1) ss += __shfl_xor_sync(0xffffffffu, ss, off);

    __shared__ float red[4];
    __shared__ float xs[128];
    if ((d & 31) == 0) red[d >> 5] = ss;
    __syncthreads();
    ss = red[0] + red[1] + red[2] + red[3];

    float xn = x * rsqrtf(ss * (1.0f / 128.0f) + 1e-6f) * w[d];
    xs[d] = xn;
    __syncthreads();
    float rot = (d < 64) ? -xs[d + 64] : xs[d - 64];

    float fi = (float)(d & 63);
    float ang = (float)pos * powf(10000.0f, -fi * (1.0f / 64.0f));
    float sn, cs;
    sincosf(ang, &sn, &cs);
    float r = xn * cs + rot * sn;
    if (isq) qb[idx] = r;
    else     kt[idx] = f2tf32(r);
}

// ---------------------------------------------------------------------------
// Tensor-core causal flash attention (tf32 mma), cp.async double-buffered K/V.
// Q-tile 128 rows, KV-tile 64. 8 warps. grid = (SEQ/128, NH), reversed qt.
// SMEM words: K0[64][128]@0  V0[128][64]@8192  K1@16384  V1@24576
//             P[128][72]@32768 ; Q staging [128][136]@16384 (pre-loop only)
// ---------------------------------------------------------------------------
#define ATTN_SMEM_WORDS 41984

__global__ __launch_bounds__(256, 1) void attn_mma(
    const float* __restrict__ q, const uint32_t* __restrict__ kt,
    const uint32_t* __restrict__ vt, uint32_t* __restrict__ o)
{
    extern __shared__ uint32_t sw[];
    uint32_t* sP = sw + 32768;    // [128][72]
    uint32_t* sQ = sw + 16384;    // staging [128][136]
    const uint32_t sbyte = smem_u32(sw);

    const int qt = gridDim.x - 1 - blockIdx.x;   // heavy tiles first
    const int h = blockIdx.y;
    const int kvh = h >> 2;
    const int qrow0 = qt * 128;
    const int tid = threadIdx.x;
    const int w = tid >> 5, lane = tid & 31;
    const int gg = lane >> 2, t = lane & 3;
    const int m0 = w * 16;
    const int jmax = 2 * qt + 2;

    // issue cp.async for KV tile jt into buffer b
    auto issueKV = [&](int b, int jt) {
        const uint32_t kb0 = sbyte + (uint32_t)(b ? 16384 : 0) * 4u;
        const uint32_t vb0 = kb0 + 8192u * 4u;
#pragma unroll
        for (int i = 0; i < 8; ++i) {      // K: 64 rows x 32 chunks
            int id = tid + i * 256;
            int r = id >> 5, c = id & 31;
            int cs = (c & 24) | ((c & 7) ^ (r & 7));
            CP_ASYNC_CG(kb0 + (uint32_t)(r * 128 + cs * 4) * 4u,
                        kt + (size_t)(jt * 64 + r) * KVD + kvh * HD + c * 4);
        }
#pragma unroll
        for (int i = 0; i < 8; ++i) {      // V: 128 rows x 16 chunks
            int id = tid + i * 256;
            int r = id >> 4, c = id & 15;
            int cs = (c & 8) | ((c & 7) ^ (r & 7));
            CP_ASYNC_CG(vb0 + (uint32_t)(r * 64 + cs * 4) * 4u,
                        vt + (size_t)(kvh * HD + r) * SEQ + jt * 64 + c * 4);
        }
    };

    // tile 0 copy overlaps Q staging (buf0 does not alias sQ)
    issueKV(0, 0); CP_COMMIT();

    // ---- stage Q tile into permuted smem (coalesced) ----
#pragma unroll
    for (int i = 0; i < 16; ++i) {
        int id = tid + i * 256;
        int r = id >> 5, c4 = id & 31, c = c4 * 4;
        float4 val = *(const float4*)(q + (size_t)(qrow0 + r) * QD + h * HD + c);
        uint32_t base = (uint32_t)(r * 136 + (c >> 3) * 8 + ((c >> 2) & 1));
        sQ[base + 0] = f2tf32(val.x);
        sQ[base + 2] = f2tf32(val.y);
        sQ[base + 4] = f2tf32(val.z);
        sQ[base + 6] = f2tf32(val.w);
    }
    __syncthreads();

    // ---- load Q fragments into registers ----
    uint32_t qf[16][4];
#pragma unroll
    for (int ks = 0; ks < 16; ++ks) {
        uint2 q0 = *(const uint2*)&sQ[(m0 + gg) * 136 + ks * 8 + 2 * t];
        uint2 q1 = *(const uint2*)&sQ[(m0 + gg + 8) * 136 + ks * 8 + 2 * t];
        qf[ks][0] = q0.x; qf[ks][1] = q1.x; qf[ks][2] = q0.y; qf[ks][3] = q1.y;
    }

    float oacc[16][4];
#pragma unroll
    for (int i = 0; i < 16; ++i)
#pragma unroll
        for (int j = 0; j < 4; ++j) oacc[i][j] = 0.0f;
    float mrow0 = -1e30f, mrow1 = -1e30f, lrow0 = 0.0f, lrow1 = 0.0f;

    const float scale = 0.08838834764831845f;  // 1/sqrt(128)

    for (int jt = 0; jt < jmax; ++jt) {
        CP_WAIT0();
        __syncthreads();   // tile jt visible to all; all warps done with prev compute
        if (jt + 1 < jmax) { issueKV((jt + 1) & 1, jt + 1); CP_COMMIT(); }

        const uint32_t* sK = sw + ((jt & 1) ? 16384 : 0);
        const uint32_t* sV = sK + 8192;

        const bool active = (jt * 64 <= qrow0 + m0 + 15);
        if (active) {
            // ---- S = Q @ K^T ----
            float sacc[8][4];
#pragma unroll
            for (int i = 0; i < 8; ++i)
#pragma unroll
                for (int j = 0; j < 4; ++j) sacc[i][j] = 0.0f;

#pragma unroll
            for (int ks = 0; ks < 16; ++ks) {
                const int c0 = ((2 * ks) & 24) | (((2 * ks) & 7) ^ gg);
                const int c1 = ((2 * ks) & 24) | ((((2 * ks) & 7) ^ 1) ^ gg);
#pragma unroll
                for (int nt = 0; nt < 8; ++nt) {
                    int nr = nt * 8 + gg;
                    mma_tf32_2(sacc[nt], qf[ks],
                               sK[nr * 128 + c0 * 4 + t], sK[nr * 128 + c1 * 4 + t]);
                }
            }

            // ---- scale + mask + online softmax ----
            const int r0 = qrow0 + m0 + gg;
            const int r1 = r0 + 8;
            const bool edge = (jt >= 2 * qt);
            float rm0 = -1e30f, rm1 = -1e30f;
#pragma unroll
            for (int nt = 0; nt < 8; ++nt) {
                float c0 = sacc[nt][0] * scale, c1 = sacc[nt][1] * scale;
                float c2 = sacc[nt][2] * scale, c3 = sacc[nt][3] * scale;
                if (edge) {
                    int colb = jt * 64 + nt * 8 + 2 * t;
                    if (colb     > r0) c0 = -1e30f;
                    if (colb + 1 > r0) c1 = -1e30f;
                    if (colb     > r1) c2 = -1e30f;
                    if (colb + 1 > r1) c3 = -1e30f;
                }
                sacc[nt][0] = c0; sacc[nt][1] = c1; sacc[nt][2] = c2; sacc[nt][3] = c3;
                rm0 = fmaxf(rm0, fmaxf(c0, c1));
                rm1 = fmaxf(rm1, fmaxf(c2, c3));
            }
            rm0 = fmaxf(rm0, __shfl_xor_sync(0xffffffffu, rm0, 1));
            rm0 = fmaxf(rm0, __shfl_xor_sync(0xffffffffu, rm0, 2));
            rm1 = fmaxf(rm1, __shfl_xor_sync(0xffffffffu, rm1, 1));
            rm1 = fmaxf(rm1, __shfl_xor_sync(0xffffffffu, rm1, 2));

            float mn0 = fmaxf(mrow0, rm0), mn1 = fmaxf(mrow1, rm1);
            float al0 = __expf(mrow0 - mn0), al1 = __expf(mrow1 - mn1);
            mrow0 = mn0; mrow1 = mn1;

            const uint32_t pA = (uint32_t)(((2 * t) & 3) * 2 + ((t >> 1) & 1));
            const uint32_t pb0 = (uint32_t)((m0 + gg) * 72) + pA;
            const uint32_t pb1 = pb0 + 8 * 72;
            float rs0 = 0.0f, rs1 = 0.0f;
#pragma unroll
            for (int nt = 0; nt < 8; ++nt) {
                float p0 = __expf(sacc[nt][0] - mn0);
                float p1 = __expf(sacc[nt][1] - mn0);
                float p2 = __expf(sacc[nt][2] - mn1);
                float p3 = __expf(sacc[nt][3] - mn1);
                rs0 += p0 + p1; rs1 += p2 + p3;
                sP[pb0 + nt * 8]     = f2tf32(p0);
                sP[pb0 + nt * 8 + 2] = f2tf32(p1);
                sP[pb1 + nt * 8]     = f2tf32(p2);
                sP[pb1 + nt * 8 + 2] = f2tf32(p3);
            }
            rs0 += __shfl_xor_sync(0xffffffffu, rs0, 1);
            rs0 += __shfl_xor_sync(0xffffffffu, rs0, 2);
            rs1 += __shfl_xor_sync(0xffffffffu, rs1, 1);
            rs1 += __shfl_xor_sync(0xffffffffu, rs1, 2);
            lrow0 = lrow0 * al0 + rs0;
            lrow1 = lrow1 * al1 + rs1;

#pragma unroll
            for (int nt = 0; nt < 16; ++nt) {
                oacc[nt][0] *= al0; oacc[nt][1] *= al0;
                oacc[nt][2] *= al1; oacc[nt][3] *= al1;
            }
            __syncwarp();

            // ---- O += P @ V ----
#pragma unroll
            for (int ks = 0; ks < 8; ++ks) {
                const int c0 = ((2 * ks) & 8) | (((2 * ks) & 7) ^ gg);
                const int c1 = ((2 * ks) & 8) | ((((2 * ks) & 7) ^ 1) ^ gg);
                uint2 pa0 = *(const uint2*)&sP[(m0 + gg) * 72 + ks * 8 + 2 * t];
                uint2 pa1 = *(const uint2*)&sP[(m0 + gg + 8) * 72 + ks * 8 + 2 * t];
                uint32_t a[4] = {pa0.x, pa1.x, pa0.y, pa1.y};
#pragma unroll
                for (int nt = 0; nt < 16; ++nt) {
                    int nr = nt * 8 + gg;
                    mma_tf32_2(oacc[nt], a,
                               sV[nr * 64 + c0 * 4 + t], sV[nr * 64 + c1 * 4 + t]);
                }
            }
        }
    }

    // ---- normalize + write tf32 bits ----
    const float inv0 = 1.0f / lrow0, inv1 = 1.0f / lrow1;
    const int r0 = qrow0 + m0 + gg;
#pragma unroll
    for (int nt = 0; nt < 16; ++nt) {
        int cc = h * HD + nt * 8 + 2 * t;
        *(uint2*)(o + (size_t)r0 * QD + cc) =
            make_uint2(f2tf32(oacc[nt][0] * inv0), f2tf32(oacc[nt][1] * inv0));
        *(uint2*)(o + (size_t)(r0 + 8) * QD + cc) =
            make_uint2(f2tf32(oacc[nt][2] * inv1), f2tf32(oacc[nt][3] * inv1));
    }
}

// ---------------------------------------------------------------------------
extern "C" void kernel_launch(void* const* d_in, const int* in_sizes, int n_in,
                              void* d_out, int out_size)
{
    (void)in_sizes; (void)n_in; (void)out_size;
    const float* x   = (const float*)d_in[0];
    const float* mu  = (const float*)d_in[1];
    const float* wq  = (const float*)d_in[2];
    const float* wk  = (const float*)d_in[3];
    const float* wv  = (const float*)d_in[4];
    const float* wo  = (const float*)d_in[5];
    const float* wmq = (const float*)d_in[6];
    const float* wmk = (const float*)d_in[7];
    const float* wmv = (const float*)d_in[8];
    const float* qw  = (const float*)d_in[9];
    const float* kw  = (const float*)d_in[10];
    float* out = (float*)d_out;

    float *pq, *pk; uint32_t *pkt, *pvt, *po;
    uint32_t *pxmu, *pwqc, *pwkc, *pwvc, *pwot;
    cudaGetSymbolAddress((void**)&pq, g_q);
    cudaGetSymbolAddress((void**)&pk, g_k);
    cudaGetSymbolAddress((void**)&pkt, g_kt);
    cudaGetSymbolAddress((void**)&pvt, g_vt);
    cudaGetSymbolAddress((void**)&po, g_o);
    cudaGetSymbolAddress((void**)&pxmu, g_xmu);
    cudaGetSymbolAddress((void**)&pwqc, g_wqc);
    cudaGetSymbolAddress((void**)&pwkc, g_wkc);
    cudaGetSymbolAddress((void**)&pwvc, g_wvc);
    cudaGetSymbolAddress((void**)&pwot, g_wot);

    // ---- prepass: convert + concat to tf32 bits ----
    cvt_cat<<<(SEQ * 2 * HID) / 1024, 256>>>(pxmu, x, mu, HID, 2 * HID);
    cvt_cat<<<(QD * 2 * HID) / 1024, 256>>>(pwqc, wq, wmq, HID, 2 * HID);
    cvt_cat<<<(KVD * 2 * HID) / 1024, 256>>>(pwkc, wk, wmk, HID, 2 * HID);
    cvt_cat<<<(KVD * 2 * HID) / 1024, 256>>>(pwvc, wv, wmv, HID, 2 * HID);
    cvt_plain<<<(HID * QD) / 1024, 256>>>(pwot, wo);

    const int gemm_smem = 3 * STAGE_WORDS * 4;  // 98304 bytes
    cudaFuncSetAttribute(qkv_mma,   cudaFuncAttributeMaxDynamicSharedMemorySize, gemm_smem);
    cudaFuncSetAttribute(oproj_mma, cudaFuncAttributeMaxDynamicSharedMemorySize, gemm_smem);

    // Fused QKV projections (tf32, cp.async pipelined, 2 CTAs/SM)
    qkv_mma<<<dim3(24, 16), 256, gemm_smem>>>(pxmu, pwqc, pwkc, pwvc, pq, pk, pvt);

    // per-head RMSNorm + RoPE; K emitted as tf32 bits
    normrope_kernel<<<dim3(SEQ, NH + NKV), 128>>>(pq, pk, pkt, qw, kw);

    // causal GQA attention (tf32, cp.async double-buffered K/V)
    const int attn_smem = ATTN_SMEM_WORDS * 4;  // 167936 bytes
    cudaFuncSetAttribute(attn_mma, cudaFuncAttributeMaxDynamicSharedMemorySize, attn_smem);
    attn_mma<<<dim3(SEQ / 128, NH), 256, attn_smem>>>(pq, pkt, pvt, po);

    // output projection (tf32, cp.async pipelined, 2 CTAs/SM)
    oproj_mma<<<dim3(16, 16), 256, gemm_smem>>>(po, pwot, out);
}